// round 1
// baseline (speedup 1.0000x reference)
#include <cuda_runtime.h>
#include <math.h>

#define HIDDEN 1024
#define NHEAD  16
#define HD     64
#define BATCH  2
#define SEQ    2048
#define MROWS  (BATCH*SEQ)   // 4096

// Scratch (static device memory — no allocations allowed)
__device__ float g_Q[BATCH*NHEAD*SEQ*HD];  // [b,h,s,d]
__device__ float g_K[BATCH*NHEAD*SEQ*HD];
__device__ float g_V[BATCH*NHEAD*SEQ*HD];
__device__ float g_O[MROWS*HIDDEN];        // [b,s,h*64+d] plain rows

// ---------------------------------------------------------------------------
// GEMM: C[m,n] = sum_k A[m,k] * W[n,k]   (A:[4096,1024], W:[1024,1024], both K-major)
// 128x128 block tile, 256 threads, 8x8 per-thread microtile, K-step 8.
// mode 0: A = x, W selected by blockIdx.z (Wq/Wk/Wv), scatter-write to g_Q/g_K/g_V
// mode 1: A = g_O, W = Wa (=Wo), plain write to Cout
// ---------------------------------------------------------------------------
__global__ __launch_bounds__(256) void gemm_kernel(
    const float* __restrict__ x,
    const float* __restrict__ Wa,
    const float* __restrict__ Wb,
    const float* __restrict__ Wc,
    float* __restrict__ Cout,
    int mode)
{
    __shared__ float As[8][128];
    __shared__ float Bs[8][128];

    const int tid  = threadIdx.x;
    const int tx   = tid & 15;
    const int ty   = tid >> 4;
    const int brow = blockIdx.y << 7;
    const int bcol = blockIdx.x << 7;
    const int z    = blockIdx.z;

    const float* A = (mode == 0) ? x : g_O;
    const float* W = (mode == 0) ? (z == 0 ? Wa : (z == 1 ? Wb : Wc)) : Wa;

    const int lrow = tid >> 1;        // 0..127
    const int lk   = (tid & 1) << 2;  // 0 or 4

    const float* Ap = A + (brow + lrow) * HIDDEN + lk;
    const float* Wp = W + (bcol + lrow) * HIDDEN + lk;

    float acc[8][8];
    #pragma unroll
    for (int i = 0; i < 8; i++)
        #pragma unroll
        for (int j = 0; j < 8; j++) acc[i][j] = 0.f;

    for (int k0 = 0; k0 < HIDDEN; k0 += 8) {
        float4 a4 = *(const float4*)(Ap + k0);
        float4 b4 = *(const float4*)(Wp + k0);
        __syncthreads();
        As[lk+0][lrow] = a4.x; As[lk+1][lrow] = a4.y;
        As[lk+2][lrow] = a4.z; As[lk+3][lrow] = a4.w;
        Bs[lk+0][lrow] = b4.x; Bs[lk+1][lrow] = b4.y;
        Bs[lk+2][lrow] = b4.z; Bs[lk+3][lrow] = b4.w;
        __syncthreads();
        #pragma unroll
        for (int kk = 0; kk < 8; kk++) {
            float ar[8], br[8];
            *(float4*)&ar[0] = *(const float4*)&As[kk][ty << 3];
            *(float4*)&ar[4] = *(const float4*)&As[kk][(ty << 3) + 4];
            *(float4*)&br[0] = *(const float4*)&Bs[kk][tx << 3];
            *(float4*)&br[4] = *(const float4*)&Bs[kk][(tx << 3) + 4];
            #pragma unroll
            for (int i = 0; i < 8; i++)
                #pragma unroll
                for (int j = 0; j < 8; j++)
                    acc[i][j] += ar[i] * br[j];
        }
    }

    #pragma unroll
    for (int i = 0; i < 8; i++) {
        const int m = brow + (ty << 3) + i;
        #pragma unroll
        for (int jj = 0; jj < 8; jj += 4) {
            const int n = bcol + (tx << 3) + jj;
            float4 v = make_float4(acc[i][jj], acc[i][jj+1], acc[i][jj+2], acc[i][jj+3]);
            if (mode == 0) {
                const int b = m >> 11, s = m & 2047;
                const int h = n >> 6,  d = n & 63;
                float* dst = (z == 0) ? g_Q : (z == 1 ? g_K : g_V);
                *(float4*)&dst[(((((b << 4) + h) << 11) + s) << 6) + d] = v;
            } else {
                *(float4*)&Cout[m * HIDDEN + n] = v;
            }
        }
    }
}

// ---------------------------------------------------------------------------
// Flash attention (no mask): per (b,h) head, online softmax over all 2048 keys.
// Block: 64 query rows x 64-key tiles, 256 threads (8 warps x 8 rows; 4 lanes/row).
// Lane (row r, quad q) owns score cols / output dims {4q + 16k + i : k,i in 0..3}.
// ---------------------------------------------------------------------------
#define AST 68                              // padded smem row stride (floats)
#define ATTN_SMEM (4 * 64 * AST * 4)        // Qs, Ks, Vs, Ps = 69632 bytes

__global__ __launch_bounds__(256) void attn_kernel()
{
    extern __shared__ float smf[];
    float* Qs = smf;
    float* Ks = smf + 64 * AST;
    float* Vs = smf + 2 * 64 * AST;
    float* Ps = smf + 3 * 64 * AST;

    const int tid  = threadIdx.x;
    const int warp = tid >> 5;
    const int lane = tid & 31;
    const int r    = (warp << 3) + (lane >> 2);  // query row in tile, 0..63
    const int quad = lane & 3;
    const int qt   = blockIdx.x;                 // query tile 0..31
    const int bh   = blockIdx.y;                 // 0..31

    const float* Qg = g_Q + ((size_t)bh << 17) + ((size_t)qt << 12);
    const float* Kb = g_K + ((size_t)bh << 17);
    const float* Vb = g_V + ((size_t)bh << 17);

    // Load Q tile, folding in the 1/sqrt(64) score scale
    for (int i = tid; i < 1024; i += 256) {
        const int row = i >> 4, c4 = (i & 15) << 2;
        float4 v = *(const float4*)&Qg[(row << 6) + c4];
        v.x *= 0.125f; v.y *= 0.125f; v.z *= 0.125f; v.w *= 0.125f;
        *(float4*)&Qs[row * AST + c4] = v;
    }

    float mi = -INFINITY, li = 0.f;
    float acc[16];
    #pragma unroll
    for (int j = 0; j < 16; j++) acc[j] = 0.f;

    for (int kt = 0; kt < 32; kt++) {
        const float* Kg = Kb + ((size_t)kt << 12);
        const float* Vg = Vb + ((size_t)kt << 12);
        __syncthreads();   // previous tile fully consumed
        for (int i = tid; i < 1024; i += 256) {
            const int row = i >> 4, c4 = (i & 15) << 2;
            *(float4*)&Ks[row * AST + c4] = *(const float4*)&Kg[(row << 6) + c4];
            *(float4*)&Vs[row * AST + c4] = *(const float4*)&Vg[(row << 6) + c4];
        }
        __syncthreads();

        // S = Q K^T for this lane's 16 columns
        float s[16];
        #pragma unroll
        for (int j = 0; j < 16; j++) s[j] = 0.f;
        const float* qrow = Qs + r * AST;
        #pragma unroll 4
        for (int d4 = 0; d4 < 64; d4 += 4) {
            const float4 q = *(const float4*)(qrow + d4);
            #pragma unroll
            for (int kk = 0; kk < 4; kk++) {
                #pragma unroll
                for (int i = 0; i < 4; i++) {
                    const float4 k = *(const float4*)&Ks[((quad << 2) + (kk << 4) + i) * AST + d4];
                    s[(kk << 2) + i] += q.x * k.x + q.y * k.y + q.z * k.z + q.w * k.w;
                }
            }
        }

        // Online softmax (row spread over 4 lanes of a quad)
        float tmax = s[0];
        #pragma unroll
        for (int j = 1; j < 16; j++) tmax = fmaxf(tmax, s[j]);
        tmax = fmaxf(tmax, __shfl_xor_sync(0xffffffffu, tmax, 1));
        tmax = fmaxf(tmax, __shfl_xor_sync(0xffffffffu, tmax, 2));
        const float mnew = fmaxf(mi, tmax);
        const float corr = __expf(mi - mnew);
        float psum = 0.f;
        #pragma unroll
        for (int j = 0; j < 16; j++) {
            const float p = __expf(s[j] - mnew);
            s[j] = p; psum += p;
        }
        psum += __shfl_xor_sync(0xffffffffu, psum, 1);
        psum += __shfl_xor_sync(0xffffffffu, psum, 2);
        li = li * corr + psum;
        mi = mnew;
        #pragma unroll
        for (int j = 0; j < 16; j++) acc[j] *= corr;

        // Stage P in smem (warp-private rows), then O += P @ V
        float* prow = Ps + r * AST;
        #pragma unroll
        for (int kk = 0; kk < 4; kk++)
            *(float4*)&prow[(quad << 2) + (kk << 4)] =
                make_float4(s[kk*4], s[kk*4+1], s[kk*4+2], s[kk*4+3]);
        __syncwarp();
        #pragma unroll 4
        for (int j = 0; j < 64; j++) {
            const float p = prow[j];
            #pragma unroll
            for (int k = 0; k < 4; k++) {
                const float4 v = *(const float4*)&Vs[j * AST + (quad << 2) + (k << 4)];
                acc[(k << 2) + 0] += p * v.x;
                acc[(k << 2) + 1] += p * v.y;
                acc[(k << 2) + 2] += p * v.z;
                acc[(k << 2) + 3] += p * v.w;
            }
        }
    }

    // Epilogue: normalize and write to g_O in [b,s,1024] layout
    const float inv = 1.f / li;
    const int sglob = (qt << 6) + r;
    const int b = bh >> 4, h = bh & 15;
    float* op = g_O + ((size_t)((b << 11) + sglob) << 10) + (h << 6);
    #pragma unroll
    for (int k = 0; k < 4; k++) {
        float4 v = make_float4(acc[k*4] * inv, acc[k*4+1] * inv,
                               acc[k*4+2] * inv, acc[k*4+3] * inv);
        *(float4*)&op[(quad << 2) + (k << 4)] = v;
    }
}

// ---------------------------------------------------------------------------
extern "C" void kernel_launch(void* const* d_in, const int* in_sizes, int n_in,
                              void* d_out, int out_size)
{
    const float* x  = (const float*)d_in[0];
    const float* Wq = (const float*)d_in[1];
    const float* Wk = (const float*)d_in[2];
    const float* Wv = (const float*)d_in[3];
    const float* Wo = (const float*)d_in[4];
    float* out = (float*)d_out;

    cudaFuncSetAttribute(attn_kernel,
                         cudaFuncAttributeMaxDynamicSharedMemorySize, ATTN_SMEM);

    // 1) Q,K,V projections (one launch, z picks the weight)
    dim3 gqkv(HIDDEN / 128, MROWS / 128, 3);
    gemm_kernel<<<gqkv, 256>>>(x, Wq, Wk, Wv, nullptr, 0);

    // 2) fused flash attention -> g_O
    dim3 gattn(SEQ / 64, BATCH * NHEAD, 1);
    attn_kernel<<<gattn, 256, ATTN_SMEM>>>();

    // 3) output projection -> d_out
    dim3 gout(HIDDEN / 128, MROWS / 128, 1);
    gemm_kernel<<<gout, 256>>>(x, Wo, nullptr, nullptr, out, 1);
}

// round 4
// speedup vs baseline: 4.0171x; 4.0171x over previous
#include <cuda_runtime.h>
#include <cuda_bf16.h>
#include <stdint.h>
#include <math.h>

#define HIDDEN 1024
#define NHEAD  16
#define SEQ    2048
#define BATCH  2
#define MROWS  (BATCH*SEQ)   // 4096

// Scratch (static device memory — no allocations allowed)
__device__ float g_Q[BATCH*NHEAD*SEQ*64];  // [b,h,s,d]
__device__ float g_K[BATCH*NHEAD*SEQ*64];
__device__ float g_V[BATCH*NHEAD*SEQ*64];
__device__ float g_O[MROWS*HIDDEN];        // [b,s,1024]

// ---------------------------------------------------------------------------
// helpers
// ---------------------------------------------------------------------------
__device__ __forceinline__ uint32_t smaddr(const void* p) {
    return (uint32_t)__cvta_generic_to_shared(p);
}

__device__ __forceinline__ void ldsm4(uint32_t r[4], uint32_t addr) {
    asm volatile("ldmatrix.sync.aligned.m8n8.x4.shared.b16 {%0,%1,%2,%3},[%4];\n"
        : "=r"(r[0]), "=r"(r[1]), "=r"(r[2]), "=r"(r[3]) : "r"(addr));
}
__device__ __forceinline__ void ldsm4t(uint32_t r[4], uint32_t addr) {
    asm volatile("ldmatrix.sync.aligned.m8n8.x4.trans.shared.b16 {%0,%1,%2,%3},[%4];\n"
        : "=r"(r[0]), "=r"(r[1]), "=r"(r[2]), "=r"(r[3]) : "r"(addr));
}
__device__ __forceinline__ void mmabf(float c[4], const uint32_t a[4], const uint32_t b[2]) {
    asm volatile("mma.sync.aligned.m16n8k16.row.col.f32.bf16.bf16.f32 "
        "{%0,%1,%2,%3},{%4,%5,%6,%7},{%8,%9},{%0,%1,%2,%3};\n"
        : "+f"(c[0]), "+f"(c[1]), "+f"(c[2]), "+f"(c[3])
        : "r"(a[0]), "r"(a[1]), "r"(a[2]), "r"(a[3]), "r"(b[0]), "r"(b[1]));
}

// split a,b into (hi,hi) and (lo,lo) bf16x2 packed words; x ≈ hi + lo, err ~2^-17
__device__ __forceinline__ void split2(float a, float b, uint32_t& h, uint32_t& l) {
    __nv_bfloat16 ah = __float2bfloat16(a);
    __nv_bfloat16 bh = __float2bfloat16(b);
    __nv_bfloat16 al = __float2bfloat16(a - __bfloat162float(ah));
    __nv_bfloat16 bl = __float2bfloat16(b - __bfloat162float(bh));
    __nv_bfloat162 hv; hv.x = ah; hv.y = bh;
    __nv_bfloat162 lv; lv.x = al; lv.y = bl;
    h = *reinterpret_cast<uint32_t*>(&hv);
    l = *reinterpret_cast<uint32_t*>(&lv);
}

// ---------------------------------------------------------------------------
// GEMM: C[m,n] = sum_k A[m,k]*W[n,k], M=4096, N=K=1024, bf16-split mma.
// 128x128 tile, 256 thr, 8 warps 2x4 (warp tile 64x32), K-chunk 32.
// mode 0: A=x, W by blockIdx.z (Wq/Wk/Wv), scatter to g_Q/g_K/g_V [b,h,s,d]
// mode 1: A=g_O, W=Wa(=Wo), plain rows to Cout
// ---------------------------------------------------------------------------
#define GSK 40   // smem row stride in bf16 (32 data + 8 pad)

__global__ __launch_bounds__(256, 1) void gemm_bf16(
    const float* __restrict__ x,
    const float* __restrict__ Wa,
    const float* __restrict__ Wb,
    const float* __restrict__ Wc,
    float* __restrict__ Cout,
    int mode)
{
    __shared__ __nv_bfloat16 Ah[128*GSK], Al[128*GSK], Bh[128*GSK], Bl[128*GSK];

    const int tid  = threadIdx.x;
    const int lane = tid & 31;
    const int warp = tid >> 5;
    const int g    = lane >> 2;
    const int t    = lane & 3;
    const int wm   = warp >> 2;          // 0..1
    const int wn   = warp & 3;           // 0..3
    const int brow = blockIdx.y << 7;
    const int bcol = blockIdx.x << 7;

    const float* A = (mode == 0) ? x : g_O;
    const float* W = (mode == 0) ? (blockIdx.z == 0 ? Wa : (blockIdx.z == 1 ? Wb : Wc)) : Wa;

    const int lr = tid >> 1;             // 0..127
    const int lh = tid & 1;              // 0..1, 16 cols each
    const float* Ap = A + (size_t)(brow + lr) * HIDDEN + lh * 16;
    const float* Wp = W + (size_t)(bcol + lr) * HIDDEN + lh * 16;
    __nv_bfloat16* sAh = Ah + lr * GSK + lh * 16;
    __nv_bfloat16* sAl = Al + lr * GSK + lh * 16;
    __nv_bfloat16* sBh = Bh + lr * GSK + lh * 16;
    __nv_bfloat16* sBl = Bl + lr * GSK + lh * 16;

    float acc[4][4][4];
    #pragma unroll
    for (int i = 0; i < 4; i++)
        #pragma unroll
        for (int j = 0; j < 4; j++)
            #pragma unroll
            for (int k = 0; k < 4; k++) acc[i][j][k] = 0.f;

    float4 ra[4], rb[4];
    #pragma unroll
    for (int i = 0; i < 4; i++) {
        ra[i] = *(const float4*)(Ap + i * 4);
        rb[i] = *(const float4*)(Wp + i * 4);
    }

    for (int kc = 0; kc < 32; kc++) {
        __syncthreads();
        // convert + store current chunk
        {
            uint32_t h8[8], l8[8];
            #pragma unroll
            for (int i = 0; i < 4; i++) {
                split2(ra[i].x, ra[i].y, h8[2*i], l8[2*i]);
                split2(ra[i].z, ra[i].w, h8[2*i+1], l8[2*i+1]);
            }
            ((uint4*)sAh)[0] = make_uint4(h8[0], h8[1], h8[2], h8[3]);
            ((uint4*)sAh)[1] = make_uint4(h8[4], h8[5], h8[6], h8[7]);
            ((uint4*)sAl)[0] = make_uint4(l8[0], l8[1], l8[2], l8[3]);
            ((uint4*)sAl)[1] = make_uint4(l8[4], l8[5], l8[6], l8[7]);
            #pragma unroll
            for (int i = 0; i < 4; i++) {
                split2(rb[i].x, rb[i].y, h8[2*i], l8[2*i]);
                split2(rb[i].z, rb[i].w, h8[2*i+1], l8[2*i+1]);
            }
            ((uint4*)sBh)[0] = make_uint4(h8[0], h8[1], h8[2], h8[3]);
            ((uint4*)sBh)[1] = make_uint4(h8[4], h8[5], h8[6], h8[7]);
            ((uint4*)sBl)[0] = make_uint4(l8[0], l8[1], l8[2], l8[3]);
            ((uint4*)sBl)[1] = make_uint4(l8[4], l8[5], l8[6], l8[7]);
        }
        __syncthreads();
        if (kc < 31) {
            #pragma unroll
            for (int i = 0; i < 4; i++) {
                ra[i] = *(const float4*)(Ap + (kc + 1) * 32 + i * 4);
                rb[i] = *(const float4*)(Wp + (kc + 1) * 32 + i * 4);
            }
        }
        // two k16 steps
        #pragma unroll
        for (int ks = 0; ks < 2; ks++) {
            uint32_t aH[4][4], aL[4][4], bH[8], bL[8];
            #pragma unroll
            for (int mi = 0; mi < 4; mi++) {
                int off = (wm * 64 + mi * 16 + (lane & 15)) * GSK + ks * 16 + (lane >> 4) * 8;
                ldsm4(aH[mi], smaddr(Ah + off));
                ldsm4(aL[mi], smaddr(Al + off));
            }
            #pragma unroll
            for (int p = 0; p < 2; p++) {
                int off = (wn * 32 + p * 16 + (lane & 7) + ((lane >> 4) & 1) * 8) * GSK
                        + ks * 16 + ((lane >> 3) & 1) * 8;
                ldsm4(&bH[p * 4], smaddr(Bh + off));
                ldsm4(&bL[p * 4], smaddr(Bl + off));
            }
            #pragma unroll
            for (int mi = 0; mi < 4; mi++)
                #pragma unroll
                for (int ni = 0; ni < 4; ni++) {
                    mmabf(acc[mi][ni], aH[mi], &bH[ni * 2]);
                    mmabf(acc[mi][ni], aH[mi], &bL[ni * 2]);
                    mmabf(acc[mi][ni], aL[mi], &bH[ni * 2]);
                }
        }
    }

    // epilogue
    #pragma unroll
    for (int mi = 0; mi < 4; mi++)
        #pragma unroll
        for (int ni = 0; ni < 4; ni++) {
            int m0 = brow + wm * 64 + mi * 16 + g;
            int n0 = bcol + wn * 32 + ni * 8 + 2 * t;
            float2 v0 = make_float2(acc[mi][ni][0], acc[mi][ni][1]);
            float2 v1 = make_float2(acc[mi][ni][2], acc[mi][ni][3]);
            if (mode == 0) {
                float* dst = (blockIdx.z == 0) ? g_Q : (blockIdx.z == 1 ? g_K : g_V);
                int b = m0 >> 11, s = m0 & 2047;
                int h = n0 >> 6,  d = n0 & 63;
                *(float2*)&dst[(((size_t)(b * NHEAD + h) * SEQ + s) << 6) + d] = v0;
                *(float2*)&dst[(((size_t)(b * NHEAD + h) * SEQ + (s + 8)) << 6) + d] = v1;
            } else {
                *(float2*)&Cout[(size_t)m0 * HIDDEN + n0] = v0;
                *(float2*)&Cout[(size_t)(m0 + 8) * HIDDEN + n0] = v1;
            }
        }
}

// ---------------------------------------------------------------------------
// Flash attention, bf16-split mma. Block: 128 q-rows, key tiles of 64.
// 8 warps, each owns 16 q-rows x full 64-key tile (softmax intra-warp).
// ---------------------------------------------------------------------------
#define AS 72   // smem row stride in bf16 (64 data + 8 pad)
// element offsets within dynamic smem (bf16 units)
#define O_QH 0
#define O_QL 9216
#define O_KH 18432
#define O_KL 23040
#define O_VH 27648
#define O_VL 32256
#define O_PH 36864
#define O_PL 46080
#define ATTN_SMEM_BYTES (55296 * 2)   // 110592

__global__ __launch_bounds__(256, 1) void attn_bf16()
{
    extern __shared__ __nv_bfloat16 sm[];
    __nv_bfloat16* Qh = sm + O_QH;  __nv_bfloat16* Ql = sm + O_QL;
    __nv_bfloat16* Kh = sm + O_KH;  __nv_bfloat16* Kl = sm + O_KL;
    __nv_bfloat16* Vh = sm + O_VH;  __nv_bfloat16* Vl = sm + O_VL;
    __nv_bfloat16* Ph = sm + O_PH;  __nv_bfloat16* Pl = sm + O_PL;

    const int tid  = threadIdx.x;
    const int lane = tid & 31;
    const int warp = tid >> 5;           // 0..7 -> q rows warp*16..+15
    const int g    = lane >> 2;
    const int t    = lane & 3;
    const int qt   = blockIdx.x;         // 0..15 (128 rows each)
    const int bh   = blockIdx.y;         // 0..31

    const float* Qg = g_Q + ((size_t)bh << 17) + ((size_t)qt << 13);
    const float* Kg = g_K + ((size_t)bh << 17);
    const float* Vg = g_V + ((size_t)bh << 17);

    // ---- load Q tile (scale 1/8 folded), convert to hi/lo bf16 ----
    {
        int r = tid >> 1, hf = tid & 1;
        const float* src = Qg + r * 64 + hf * 32;
        __nv_bfloat16* dh = Qh + r * AS + hf * 32;
        __nv_bfloat16* dl = Ql + r * AS + hf * 32;
        #pragma unroll
        for (int i = 0; i < 8; i++) {
            float4 f = ((const float4*)src)[i];
            f.x *= 0.125f; f.y *= 0.125f; f.z *= 0.125f; f.w *= 0.125f;
            uint32_t h0, l0, h1, l1;
            split2(f.x, f.y, h0, l0);
            split2(f.z, f.w, h1, l1);
            *(uint2*)(dh + i * 4) = make_uint2(h0, h1);
            *(uint2*)(dl + i * 4) = make_uint2(l0, l1);
        }
    }

    // per-thread K/V staging assignment: row tid>>2 (0..63), 16 cols
    const int rk = tid >> 2, q4 = tid & 3;
    const float* Kp = Kg + rk * 64 + q4 * 16;
    const float* Vp = Vg + rk * 64 + q4 * 16;
    __nv_bfloat16* dKh = Kh + rk * AS + q4 * 16;
    __nv_bfloat16* dKl = Kl + rk * AS + q4 * 16;
    __nv_bfloat16* dVh = Vh + rk * AS + q4 * 16;
    __nv_bfloat16* dVl = Vl + rk * AS + q4 * 16;

    float m0 = -1e30f, m1 = -1e30f, l0 = 0.f, l1 = 0.f;
    float accO[8][4];
    #pragma unroll
    for (int i = 0; i < 8; i++)
        #pragma unroll
        for (int j = 0; j < 4; j++) accO[i][j] = 0.f;

    float4 kreg[4], vreg[4];
    #pragma unroll
    for (int i = 0; i < 4; i++) {
        kreg[i] = *(const float4*)(Kp + i * 4);
        vreg[i] = *(const float4*)(Vp + i * 4);
    }

    for (int kt = 0; kt < 32; kt++) {
        __syncthreads();
        // stage K/V tile as hi/lo bf16
        {
            uint32_t h8[8], l8[8];
            #pragma unroll
            for (int i = 0; i < 4; i++) {
                split2(kreg[i].x, kreg[i].y, h8[2*i], l8[2*i]);
                split2(kreg[i].z, kreg[i].w, h8[2*i+1], l8[2*i+1]);
            }
            ((uint4*)dKh)[0] = make_uint4(h8[0], h8[1], h8[2], h8[3]);
            ((uint4*)dKh)[1] = make_uint4(h8[4], h8[5], h8[6], h8[7]);
            ((uint4*)dKl)[0] = make_uint4(l8[0], l8[1], l8[2], l8[3]);
            ((uint4*)dKl)[1] = make_uint4(l8[4], l8[5], l8[6], l8[7]);
            #pragma unroll
            for (int i = 0; i < 4; i++) {
                split2(vreg[i].x, vreg[i].y, h8[2*i], l8[2*i]);
                split2(vreg[i].z, vreg[i].w, h8[2*i+1], l8[2*i+1]);
            }
            ((uint4*)dVh)[0] = make_uint4(h8[0], h8[1], h8[2], h8[3]);
            ((uint4*)dVh)[1] = make_uint4(h8[4], h8[5], h8[6], h8[7]);
            ((uint4*)dVl)[0] = make_uint4(l8[0], l8[1], l8[2], l8[3]);
            ((uint4*)dVl)[1] = make_uint4(l8[4], l8[5], l8[6], l8[7]);
        }
        __syncthreads();
        if (kt < 31) {
            #pragma unroll
            for (int i = 0; i < 4; i++) {
                kreg[i] = *(const float4*)(Kp + (kt + 1) * 4096 + i * 4);
                vreg[i] = *(const float4*)(Vp + (kt + 1) * 4096 + i * 4);
            }
        }

        // ---- S = Q K^T over this key tile ----
        float accS[8][4];
        #pragma unroll
        for (int i = 0; i < 8; i++)
            #pragma unroll
            for (int j = 0; j < 4; j++) accS[i][j] = 0.f;

        #pragma unroll
        for (int c = 0; c < 4; c++) {
            uint32_t aH[4], aL[4], bH[16], bL[16];
            int aoff = (warp * 16 + (lane & 15)) * AS + c * 16 + (lane >> 4) * 8;
            ldsm4(aH, smaddr(Qh + aoff));
            ldsm4(aL, smaddr(Ql + aoff));
            #pragma unroll
            for (int p = 0; p < 4; p++) {
                int boff = (p * 16 + (lane & 7) + ((lane >> 4) & 1) * 8) * AS
                         + c * 16 + ((lane >> 3) & 1) * 8;
                ldsm4(&bH[p * 4], smaddr(Kh + boff));
                ldsm4(&bL[p * 4], smaddr(Kl + boff));
            }
            #pragma unroll
            for (int nt = 0; nt < 8; nt++) {
                mmabf(accS[nt], aH, &bH[nt * 2]);
                mmabf(accS[nt], aH, &bL[nt * 2]);
                mmabf(accS[nt], aL, &bH[nt * 2]);
            }
        }

        // ---- online softmax (rows g, g+8 of this warp's 16 rows) ----
        float mx0 = accS[0][0], mx1 = accS[0][2];
        #pragma unroll
        for (int nt = 0; nt < 8; nt++) {
            mx0 = fmaxf(mx0, fmaxf(accS[nt][0], accS[nt][1]));
            mx1 = fmaxf(mx1, fmaxf(accS[nt][2], accS[nt][3]));
        }
        mx0 = fmaxf(mx0, __shfl_xor_sync(0xffffffffu, mx0, 1));
        mx0 = fmaxf(mx0, __shfl_xor_sync(0xffffffffu, mx0, 2));
        mx1 = fmaxf(mx1, __shfl_xor_sync(0xffffffffu, mx1, 1));
        mx1 = fmaxf(mx1, __shfl_xor_sync(0xffffffffu, mx1, 2));
        const float nm0 = fmaxf(m0, mx0), nm1 = fmaxf(m1, mx1);
        const float cr0 = __expf(m0 - nm0), cr1 = __expf(m1 - nm1);
        float s0 = 0.f, s1 = 0.f;
        #pragma unroll
        for (int nt = 0; nt < 8; nt++) {
            accS[nt][0] = __expf(accS[nt][0] - nm0); s0 += accS[nt][0];
            accS[nt][1] = __expf(accS[nt][1] - nm0); s0 += accS[nt][1];
            accS[nt][2] = __expf(accS[nt][2] - nm1); s1 += accS[nt][2];
            accS[nt][3] = __expf(accS[nt][3] - nm1); s1 += accS[nt][3];
        }
        s0 += __shfl_xor_sync(0xffffffffu, s0, 1);
        s0 += __shfl_xor_sync(0xffffffffu, s0, 2);
        s1 += __shfl_xor_sync(0xffffffffu, s1, 1);
        s1 += __shfl_xor_sync(0xffffffffu, s1, 2);
        l0 = l0 * cr0 + s0;  l1 = l1 * cr1 + s1;
        m0 = nm0;  m1 = nm1;
        #pragma unroll
        for (int nt = 0; nt < 8; nt++) {
            accO[nt][0] *= cr0; accO[nt][1] *= cr0;
            accO[nt][2] *= cr1; accO[nt][3] *= cr1;
        }

        // ---- stage P (warp-private rows) as hi/lo bf16 ----
        __syncwarp();
        {
            const int col = 2 * t;
            const int r0 = (warp * 16 + g) * AS;
            const int r1 = (warp * 16 + g + 8) * AS;
            #pragma unroll
            for (int nt = 0; nt < 8; nt++) {
                uint32_t h, l;
                split2(accS[nt][0], accS[nt][1], h, l);
                *(uint32_t*)(Ph + r0 + nt * 8 + col) = h;
                *(uint32_t*)(Pl + r0 + nt * 8 + col) = l;
                split2(accS[nt][2], accS[nt][3], h, l);
                *(uint32_t*)(Ph + r1 + nt * 8 + col) = h;
                *(uint32_t*)(Pl + r1 + nt * 8 + col) = l;
            }
        }
        __syncwarp();

        // ---- O += P V ----
        #pragma unroll
        for (int c = 0; c < 4; c++) {
            uint32_t aH[4], aL[4], bH[16], bL[16];
            int aoff = (warp * 16 + (lane & 15)) * AS + c * 16 + (lane >> 4) * 8;
            ldsm4(aH, smaddr(Ph + aoff));
            ldsm4(aL, smaddr(Pl + aoff));
            #pragma unroll
            for (int p = 0; p < 4; p++) {
                int boff = (c * 16 + (lane & 15)) * AS + p * 16 + (lane >> 4) * 8;
                ldsm4t(&bH[p * 4], smaddr(Vh + boff));
                ldsm4t(&bL[p * 4], smaddr(Vl + boff));
            }
            #pragma unroll
            for (int nt = 0; nt < 8; nt++) {
                mmabf(accO[nt], aH, &bH[nt * 2]);
                mmabf(accO[nt], aH, &bL[nt * 2]);
                mmabf(accO[nt], aL, &bH[nt * 2]);
            }
        }
    }

    // ---- epilogue: normalize, write g_O [b,s,1024] ----
    const float i0 = 1.f / l0, i1 = 1.f / l1;
    const int sg = qt * 128 + warp * 16 + g;
    const int b = bh >> 4, h = bh & 15;
    float* op = g_O + (size_t)(b * SEQ + sg) * HIDDEN + h * 64;
    #pragma unroll
    for (int nt = 0; nt < 8; nt++) {
        *(float2*)&op[nt * 8 + 2 * t] =
            make_float2(accO[nt][0] * i0, accO[nt][1] * i0);
        *(float2*)&op[8 * HIDDEN + nt * 8 + 2 * t] =
            make_float2(accO[nt][2] * i1, accO[nt][3] * i1);
    }
}

// ---------------------------------------------------------------------------
extern "C" void kernel_launch(void* const* d_in, const int* in_sizes, int n_in,
                              void* d_out, int out_size)
{
    const float* x  = (const float*)d_in[0];
    const float* Wq = (const float*)d_in[1];
    const float* Wk = (const float*)d_in[2];
    const float* Wv = (const float*)d_in[3];
    const float* Wo = (const float*)d_in[4];
    float* out = (float*)d_out;

    cudaFuncSetAttribute(attn_bf16,
                         cudaFuncAttributeMaxDynamicSharedMemorySize, ATTN_SMEM_BYTES);

    // 1) Q,K,V projections
    dim3 gqkv(HIDDEN / 128, MROWS / 128, 3);
    gemm_bf16<<<gqkv, 256>>>(x, Wq, Wk, Wv, nullptr, 0);

    // 2) fused flash attention -> g_O
    dim3 gattn(SEQ / 128, BATCH * NHEAD, 1);
    attn_bf16<<<gattn, 256, ATTN_SMEM_BYTES>>>();

    // 3) output projection -> d_out
    dim3 gout(HIDDEN / 128, MROWS / 128, 1);
    gemm_bf16<<<gout, 256>>>(x, Wo, nullptr, nullptr, out, 1);
}

// round 5
// speedup vs baseline: 4.5979x; 1.1446x over previous
#include <cuda_runtime.h>
#include <cuda_bf16.h>
#include <stdint.h>
#include <math.h>

#define HIDDEN 1024
#define NHEAD  16
#define SEQ    2048
#define BATCH  2
#define MROWS  (BATCH*SEQ)   // 4096

// converted input pool: [ x (4M) | Wq (1M) | Wk | Wv | Wo ]  (element counts)
#define XOFF 0
#define WOFF (4*1024*1024)
#define WSZ  (1024*1024)
#define CVT_TOTAL (8*1024*1024)

__device__ __nv_bfloat16 g_cvtH[CVT_TOTAL];
__device__ __nv_bfloat16 g_cvtL[CVT_TOTAL];

// Q/K/V in [b,h,s,d] layout, bf16 hi/lo (Q pre-scaled by 0.125)
__device__ __nv_bfloat16 g_Qh[BATCH*NHEAD*SEQ*64], g_Ql[BATCH*NHEAD*SEQ*64];
__device__ __nv_bfloat16 g_Kh[BATCH*NHEAD*SEQ*64], g_Kl[BATCH*NHEAD*SEQ*64];
__device__ __nv_bfloat16 g_Vh[BATCH*NHEAD*SEQ*64], g_Vl[BATCH*NHEAD*SEQ*64];
// attention output, [b,s,1024], bf16 hi/lo
__device__ __nv_bfloat16 g_Oh[MROWS*HIDDEN], g_Ol[MROWS*HIDDEN];

// ---------------------------------------------------------------------------
// helpers
// ---------------------------------------------------------------------------
__device__ __forceinline__ uint32_t smaddr(const void* p) {
    return (uint32_t)__cvta_generic_to_shared(p);
}
__device__ __forceinline__ void cpasync16(uint32_t s, const void* g) {
    asm volatile("cp.async.cg.shared.global [%0], [%1], 16;\n"
        :: "r"(s), "l"(__cvta_generic_to_global(g)));
}
#define CP_COMMIT() asm volatile("cp.async.commit_group;\n")
#define CP_WAIT(n)  asm volatile("cp.async.wait_group %0;\n" :: "n"(n))

__device__ __forceinline__ void ldsm4(uint32_t r[4], uint32_t addr) {
    asm volatile("ldmatrix.sync.aligned.m8n8.x4.shared.b16 {%0,%1,%2,%3},[%4];\n"
        : "=r"(r[0]), "=r"(r[1]), "=r"(r[2]), "=r"(r[3]) : "r"(addr));
}
__device__ __forceinline__ void ldsm4t(uint32_t r[4], uint32_t addr) {
    asm volatile("ldmatrix.sync.aligned.m8n8.x4.trans.shared.b16 {%0,%1,%2,%3},[%4];\n"
        : "=r"(r[0]), "=r"(r[1]), "=r"(r[2]), "=r"(r[3]) : "r"(addr));
}
__device__ __forceinline__ void mmabf(float c[4], const uint32_t a[4], const uint32_t b[2]) {
    asm volatile("mma.sync.aligned.m16n8k16.row.col.f32.bf16.bf16.f32 "
        "{%0,%1,%2,%3},{%4,%5,%6,%7},{%8,%9},{%0,%1,%2,%3};\n"
        : "+f"(c[0]), "+f"(c[1]), "+f"(c[2]), "+f"(c[3])
        : "r"(a[0]), "r"(a[1]), "r"(a[2]), "r"(a[3]), "r"(b[0]), "r"(b[1]));
}

// split a,b into packed bf16x2 hi and lo words; x ~= hi + lo (err ~2^-17)
__device__ __forceinline__ void split2(float a, float b, uint32_t& h, uint32_t& l) {
    __nv_bfloat16 ah = __float2bfloat16(a);
    __nv_bfloat16 bh = __float2bfloat16(b);
    __nv_bfloat16 al = __float2bfloat16(a - __bfloat162float(ah));
    __nv_bfloat16 bl = __float2bfloat16(b - __bfloat162float(bh));
    __nv_bfloat162 hv; hv.x = ah; hv.y = bh;
    __nv_bfloat162 lv; lv.x = al; lv.y = bl;
    h = *reinterpret_cast<uint32_t*>(&hv);
    l = *reinterpret_cast<uint32_t*>(&lv);
}

// swizzled byte offsets (conflict-free for cp.async stores + ldmatrix reads)
__device__ __forceinline__ uint32_t swz64(int row, int c16) {   // 64B rows (32 bf16)
    return (uint32_t)(row * 64 + ((c16 ^ (row & 3)) << 4));
}
__device__ __forceinline__ uint32_t swz128(int row, int c16) {  // 128B rows (64 bf16)
    return (uint32_t)(row * 128 + ((c16 ^ (row & 7)) << 4));
}

// ---------------------------------------------------------------------------
// converter: fp32 -> bf16 hi/lo pool  (x then Wq,Wk,Wv,Wo)
// ---------------------------------------------------------------------------
__global__ __launch_bounds__(256) void convert_kernel(
    const float* __restrict__ x,  const float* __restrict__ wq,
    const float* __restrict__ wk, const float* __restrict__ wv,
    const float* __restrict__ wo)
{
    const size_t idx4 = (size_t)blockIdx.x * blockDim.x + threadIdx.x; // 4 elems each
    const size_t off  = idx4 << 2;
    const float* src;
    if (off < (size_t)WOFF) {
        src = x + off;
    } else {
        const size_t wo_off = off - WOFF;
        const int w = (int)(wo_off >> 20);
        const size_t r = wo_off & (WSZ - 1);
        src = (w == 0 ? wq : w == 1 ? wk : w == 2 ? wv : wo) + r;
    }
    float4 f = *(const float4*)src;
    uint32_t h0, l0, h1, l1;
    split2(f.x, f.y, h0, l0);
    split2(f.z, f.w, h1, l1);
    *(uint2*)(g_cvtH + off) = make_uint2(h0, h1);
    *(uint2*)(g_cvtL + off) = make_uint2(l0, l1);
}

// ---------------------------------------------------------------------------
// GEMM: C[m,n] = sum_k A[m,k]*W[n,k], all operands pre-split bf16 hi/lo.
// 128x128 tile, 256 thr, 8 warps 2x4 (warp tile 64x32), K-chunk 32,
// 3-stage cp.async pipeline, swizzled smem.
// mode 0: scatter hi/lo to g_Q/K/V [b,h,s,d] (Q scaled 0.125); mode 1: fp32 rows.
// ---------------------------------------------------------------------------
#define GSTAGE 32768                  // bytes per stage: 4 comps x 128x32 bf16
#define GEMM_SMEM (3 * GSTAGE)        // 98304

__global__ __launch_bounds__(256, 1) void gemm_bf16(
    const __nv_bfloat16* __restrict__ Ah_g, const __nv_bfloat16* __restrict__ Al_g,
    const __nv_bfloat16* __restrict__ Bh_g, const __nv_bfloat16* __restrict__ Bl_g,
    float* __restrict__ Cout, int mode)
{
    extern __shared__ char dynsm[];
    const uint32_t smb = smaddr(dynsm);

    const int tid  = threadIdx.x;
    const int lane = tid & 31;
    const int warp = tid >> 5;
    const int gq   = lane >> 2;
    const int t    = lane & 3;
    const int wm   = warp >> 2;          // 0..1
    const int wn   = warp & 3;           // 0..3
    const int brow = blockIdx.y << 7;
    const int bcol = blockIdx.x << 7;
    const int z    = blockIdx.z;

    if (mode == 0) { Bh_g += (size_t)z << 20; Bl_g += (size_t)z << 20; }

    // per-thread copy assignment: row cr (0..127), chunks cc, cc+1
    const int cr = tid >> 1;
    const int cc = (tid & 1) << 1;
    const char* gAh = (const char*)(Ah_g + (size_t)(brow + cr) * HIDDEN);
    const char* gAl = (const char*)(Al_g + (size_t)(brow + cr) * HIDDEN);
    const char* gBh = (const char*)(Bh_g + (size_t)(bcol + cr) * HIDDEN);
    const char* gBl = (const char*)(Bl_g + (size_t)(bcol + cr) * HIDDEN);
    uint32_t sw0 = swz64(cr, cc), sw1 = swz64(cr, cc + 1);

    #define GCOPY(S, KC) do {                                            \
        uint32_t sb_ = smb + (S) * GSTAGE;                               \
        size_t go_ = (size_t)(KC) * 64;                                  \
        cpasync16(sb_ +     0 + sw0, gAh + go_ + cc * 16);               \
        cpasync16(sb_ +  8192 + sw0, gAl + go_ + cc * 16);               \
        cpasync16(sb_ + 16384 + sw0, gBh + go_ + cc * 16);               \
        cpasync16(sb_ + 24576 + sw0, gBl + go_ + cc * 16);               \
        cpasync16(sb_ +     0 + sw1, gAh + go_ + cc * 16 + 16);          \
        cpasync16(sb_ +  8192 + sw1, gAl + go_ + cc * 16 + 16);         \
        cpasync16(sb_ + 16384 + sw1, gBh + go_ + cc * 16 + 16);          \
        cpasync16(sb_ + 24576 + sw1, gBl + go_ + cc * 16 + 16);          \
    } while (0)

    float acc[4][4][4];
    #pragma unroll
    for (int i = 0; i < 4; i++)
        #pragma unroll
        for (int j = 0; j < 4; j++)
            #pragma unroll
            for (int k = 0; k < 4; k++) acc[i][j][k] = 0.f;

    GCOPY(0, 0); CP_COMMIT();
    GCOPY(1, 1); CP_COMMIT();

    int st = 0, stn = 2;
    for (int kc = 0; kc < 32; kc++) {
        if (kc == 31) { CP_WAIT(0); } else { CP_WAIT(1); }
        __syncthreads();
        if (kc + 2 < 32) {
            GCOPY(stn, kc + 2); CP_COMMIT();
        }
        const uint32_t sb = smb + st * GSTAGE;
        #pragma unroll
        for (int ks = 0; ks < 2; ks++) {
            uint32_t aH[4][4], aL[4][4], bH[8], bL[8];
            #pragma unroll
            for (int mi = 0; mi < 4; mi++) {
                int row = wm * 64 + mi * 16 + (lane & 15);
                int c16 = ks * 2 + (lane >> 4);
                uint32_t ad = sb + swz64(row, c16);
                ldsm4(aH[mi], ad);
                ldsm4(aL[mi], ad + 8192);
            }
            #pragma unroll
            for (int p = 0; p < 2; p++) {
                int row = wn * 32 + p * 16 + (lane & 7) + ((lane >> 4) & 1) * 8;
                int c16 = ks * 2 + ((lane >> 3) & 1);
                uint32_t bd = sb + 16384 + swz64(row, c16);
                ldsm4(&bH[p * 4], bd);
                ldsm4(&bL[p * 4], bd + 8192);
            }
            #pragma unroll
            for (int mi = 0; mi < 4; mi++)
                #pragma unroll
                for (int ni = 0; ni < 4; ni++) {
                    mmabf(acc[mi][ni], aH[mi], &bH[ni * 2]);
                    mmabf(acc[mi][ni], aH[mi], &bL[ni * 2]);
                    mmabf(acc[mi][ni], aL[mi], &bH[ni * 2]);
                }
        }
        __syncthreads();
        st = (st == 2) ? 0 : st + 1;
        stn = (stn == 2) ? 0 : stn + 1;
    }
    #undef GCOPY

    // epilogue
    const float scale = (mode == 0 && z == 0) ? 0.125f : 1.0f;
    __nv_bfloat16* dh = (z == 0) ? g_Qh : (z == 1) ? g_Kh : g_Vh;
    __nv_bfloat16* dl = (z == 0) ? g_Ql : (z == 1) ? g_Kl : g_Vl;
    #pragma unroll
    for (int mi = 0; mi < 4; mi++)
        #pragma unroll
        for (int ni = 0; ni < 4; ni++) {
            int m0 = brow + wm * 64 + mi * 16 + gq;
            int n0 = bcol + wn * 32 + ni * 8 + 2 * t;
            if (mode == 0) {
                int b = m0 >> 11, s = m0 & 2047;
                int hd = n0 >> 6, d = n0 & 63;
                size_t e0 = (((size_t)(b * NHEAD + hd) * SEQ + s) << 6) + d;
                size_t e1 = (((size_t)(b * NHEAD + hd) * SEQ + (s + 8)) << 6) + d;
                uint32_t uh, ul;
                split2(acc[mi][ni][0] * scale, acc[mi][ni][1] * scale, uh, ul);
                *(uint32_t*)&dh[e0] = uh; *(uint32_t*)&dl[e0] = ul;
                split2(acc[mi][ni][2] * scale, acc[mi][ni][3] * scale, uh, ul);
                *(uint32_t*)&dh[e1] = uh; *(uint32_t*)&dl[e1] = ul;
            } else {
                *(float2*)&Cout[(size_t)m0 * HIDDEN + n0] =
                    make_float2(acc[mi][ni][0], acc[mi][ni][1]);
                *(float2*)&Cout[(size_t)(m0 + 8) * HIDDEN + n0] =
                    make_float2(acc[mi][ni][2], acc[mi][ni][3]);
            }
        }
}

// ---------------------------------------------------------------------------
// Flash attention: 128 q-rows/block, 64-key tiles, K/V double-buffered cp.async.
// smem (bytes): Qh 0, Ql 16K, Ph 32K, Pl 48K, KV stages at 64K+32K*s
//   (stage: Kh 8K | Kl 8K | Vh 8K | Vl 8K).  Total 128K.
// ---------------------------------------------------------------------------
#define ATTN_SMEM_BYTES 131072
#define KVB(s) (65536 + (s) * 32768)

__global__ __launch_bounds__(256, 1) void attn_bf16()
{
    extern __shared__ char dynsm[];
    const uint32_t smb = smaddr(dynsm);

    const int tid  = threadIdx.x;
    const int lane = tid & 31;
    const int warp = tid >> 5;           // 0..7 -> q rows warp*16..+15
    const int gq   = lane >> 2;
    const int t    = lane & 3;
    const int qt   = blockIdx.x;         // 0..15
    const int bh   = blockIdx.y;         // 0..31

    const size_t hb = (size_t)bh << 17;

    // ---- Q tile copy (pre-scaled hi/lo bf16 in gmem) ----
    {
        const int row = tid >> 1;
        const int cb  = (tid & 1) << 2;
        const char* gqh = (const char*)(g_Qh + hb + ((size_t)qt << 13) + row * 64);
        const char* gql = (const char*)(g_Ql + hb + ((size_t)qt << 13) + row * 64);
        #pragma unroll
        for (int i = 0; i < 4; i++) {
            int c16 = cb + i;
            uint32_t sw = swz128(row, c16);
            cpasync16(smb + sw,         gqh + c16 * 16);
            cpasync16(smb + 16384 + sw, gql + c16 * 16);
        }
    }

    // per-thread K/V copy assignment
    const int kvr = tid >> 2;
    const int kvc = (tid & 3) << 1;
    const char* gkh = (const char*)(g_Kh + hb + kvr * 64);
    const char* gkl = (const char*)(g_Kl + hb + kvr * 64);
    const char* gvh = (const char*)(g_Vh + hb + kvr * 64);
    const char* gvl = (const char*)(g_Vl + hb + kvr * 64);
    const uint32_t ksw0 = swz128(kvr, kvc), ksw1 = swz128(kvr, kvc + 1);

    #define KVCOPY(S, KT) do {                                           \
        uint32_t sb_ = smb + KVB(S);                                     \
        size_t go_ = (size_t)(KT) * 8192;                                \
        cpasync16(sb_ +     0 + ksw0, gkh + go_ + kvc * 16);             \
        cpasync16(sb_ +  8192 + ksw0, gkl + go_ + kvc * 16);             \
        cpasync16(sb_ + 16384 + ksw0, gvh + go_ + kvc * 16);             \
        cpasync16(sb_ + 24576 + ksw0, gvl + go_ + kvc * 16);             \
        cpasync16(sb_ +     0 + ksw1, gkh + go_ + kvc * 16 + 16);        \
        cpasync16(sb_ +  8192 + ksw1, gkl + go_ + kvc * 16 + 16);        \
        cpasync16(sb_ + 16384 + ksw1, gvh + go_ + kvc * 16 + 16);        \
        cpasync16(sb_ + 24576 + ksw1, gvl + go_ + kvc * 16 + 16);        \
    } while (0)

    float m0 = -1e30f, m1 = -1e30f, l0 = 0.f, l1 = 0.f;
    float accO[8][4];
    #pragma unroll
    for (int i = 0; i < 8; i++)
        #pragma unroll
        for (int j = 0; j < 4; j++) accO[i][j] = 0.f;

    KVCOPY(0, 0); CP_COMMIT();

    for (int kt = 0; kt < 32; kt++) {
        CP_WAIT(0);
        __syncthreads();
        if (kt + 1 < 32) { KVCOPY((kt + 1) & 1, kt + 1); CP_COMMIT(); }
        const uint32_t kvb = smb + KVB(kt & 1);

        // ---- S = Q K^T ----
        float accS[8][4];
        #pragma unroll
        for (int i = 0; i < 8; i++)
            #pragma unroll
            for (int j = 0; j < 4; j++) accS[i][j] = 0.f;

        #pragma unroll
        for (int c = 0; c < 4; c++) {
            uint32_t aH[4], aL[4], bH[16], bL[16];
            {
                int row = warp * 16 + (lane & 15);
                int c16 = c * 2 + (lane >> 4);
                uint32_t ad = smb + swz128(row, c16);
                ldsm4(aH, ad);
                ldsm4(aL, ad + 16384);
            }
            #pragma unroll
            for (int p = 0; p < 4; p++) {
                int row = p * 16 + (lane & 7) + ((lane >> 4) & 1) * 8;
                int c16 = c * 2 + ((lane >> 3) & 1);
                uint32_t bd = kvb + swz128(row, c16);
                ldsm4(&bH[p * 4], bd);
                ldsm4(&bL[p * 4], bd + 8192);
            }
            #pragma unroll
            for (int nt = 0; nt < 8; nt++) {
                mmabf(accS[nt], aH, &bH[nt * 2]);
                mmabf(accS[nt], aH, &bL[nt * 2]);
                mmabf(accS[nt], aL, &bH[nt * 2]);
            }
        }

        // ---- online softmax ----
        float mx0 = accS[0][0], mx1 = accS[0][2];
        #pragma unroll
        for (int nt = 0; nt < 8; nt++) {
            mx0 = fmaxf(mx0, fmaxf(accS[nt][0], accS[nt][1]));
            mx1 = fmaxf(mx1, fmaxf(accS[nt][2], accS[nt][3]));
        }
        mx0 = fmaxf(mx0, __shfl_xor_sync(0xffffffffu, mx0, 1));
        mx0 = fmaxf(mx0, __shfl_xor_sync(0xffffffffu, mx0, 2));
        mx1 = fmaxf(mx1, __shfl_xor_sync(0xffffffffu, mx1, 1));
        mx1 = fmaxf(mx1, __shfl_xor_sync(0xffffffffu, mx1, 2));
        const float nm0 = fmaxf(m0, mx0), nm1 = fmaxf(m1, mx1);
        const float cr0 = __expf(m0 - nm0), cr1 = __expf(m1 - nm1);
        float s0 = 0.f, s1 = 0.f;
        #pragma unroll
        for (int nt = 0; nt < 8; nt++) {
            accS[nt][0] = __expf(accS[nt][0] - nm0); s0 += accS[nt][0];
            accS[nt][1] = __expf(accS[nt][1] - nm0); s0 += accS[nt][1];
            accS[nt][2] = __expf(accS[nt][2] - nm1); s1 += accS[nt][2];
            accS[nt][3] = __expf(accS[nt][3] - nm1); s1 += accS[nt][3];
        }
        s0 += __shfl_xor_sync(0xffffffffu, s0, 1);
        s0 += __shfl_xor_sync(0xffffffffu, s0, 2);
        s1 += __shfl_xor_sync(0xffffffffu, s1, 1);
        s1 += __shfl_xor_sync(0xffffffffu, s1, 2);
        l0 = l0 * cr0 + s0;  l1 = l1 * cr1 + s1;
        m0 = nm0;  m1 = nm1;
        #pragma unroll
        for (int nt = 0; nt < 8; nt++) {
            accO[nt][0] *= cr0; accO[nt][1] *= cr0;
            accO[nt][2] *= cr1; accO[nt][3] *= cr1;
        }

        // ---- stage P (warp-private rows) as hi/lo ----
        __syncwarp();
        {
            const int r0 = warp * 16 + gq;
            const int r1 = r0 + 8;
            #pragma unroll
            for (int nt = 0; nt < 8; nt++) {
                uint32_t ph0 = smb + 32768 + r0 * 128 + ((nt ^ (r0 & 7)) << 4) + 4 * t;
                uint32_t ph1 = smb + 32768 + r1 * 128 + ((nt ^ (r1 & 7)) << 4) + 4 * t;
                uint32_t h, l;
                split2(accS[nt][0], accS[nt][1], h, l);
                asm volatile("st.shared.b32 [%0], %1;\n" :: "r"(ph0), "r"(h));
                asm volatile("st.shared.b32 [%0], %1;\n" :: "r"(ph0 + 16384), "r"(l));
                split2(accS[nt][2], accS[nt][3], h, l);
                asm volatile("st.shared.b32 [%0], %1;\n" :: "r"(ph1), "r"(h));
                asm volatile("st.shared.b32 [%0], %1;\n" :: "r"(ph1 + 16384), "r"(l));
            }
        }
        __syncwarp();

        // ---- O += P V ----
        #pragma unroll
        for (int c = 0; c < 4; c++) {
            uint32_t aH[4], aL[4], bH[16], bL[16];
            {
                int row = warp * 16 + (lane & 15);
                int c16 = c * 2 + (lane >> 4);
                uint32_t ad = smb + 32768 + swz128(row, c16);
                ldsm4(aH, ad);
                ldsm4(aL, ad + 16384);
            }
            #pragma unroll
            for (int p = 0; p < 4; p++) {
                int row = c * 16 + (lane & 15);
                int c16 = p * 2 + (lane >> 4);
                uint32_t vd = kvb + 16384 + swz128(row, c16);
                ldsm4t(&bH[p * 4], vd);
                ldsm4t(&bL[p * 4], vd + 8192);
            }
            #pragma unroll
            for (int nt = 0; nt < 8; nt++) {
                mmabf(accO[nt], aH, &bH[nt * 2]);
                mmabf(accO[nt], aH, &bL[nt * 2]);
                mmabf(accO[nt], aL, &bH[nt * 2]);
            }
        }
        __syncthreads();
    }
    #undef KVCOPY

    // ---- epilogue: normalize, split, write g_Oh/g_Ol [b,s,1024] ----
    const float i0 = 1.f / l0, i1 = 1.f / l1;
    const int sg = qt * 128 + warp * 16 + gq;
    const int b = bh >> 4, hh = bh & 15;
    #pragma unroll
    for (int nt = 0; nt < 8; nt++) {
        size_t e0 = (size_t)(b * SEQ + sg) * HIDDEN + hh * 64 + nt * 8 + 2 * t;
        size_t e1 = e0 + (size_t)8 * HIDDEN;
        uint32_t h, l;
        split2(accO[nt][0] * i0, accO[nt][1] * i0, h, l);
        *(uint32_t*)&g_Oh[e0] = h; *(uint32_t*)&g_Ol[e0] = l;
        split2(accO[nt][2] * i1, accO[nt][3] * i1, h, l);
        *(uint32_t*)&g_Oh[e1] = h; *(uint32_t*)&g_Ol[e1] = l;
    }
}

// ---------------------------------------------------------------------------
extern "C" void kernel_launch(void* const* d_in, const int* in_sizes, int n_in,
                              void* d_out, int out_size)
{
    const float* x  = (const float*)d_in[0];
    const float* Wq = (const float*)d_in[1];
    const float* Wk = (const float*)d_in[2];
    const float* Wv = (const float*)d_in[3];
    const float* Wo = (const float*)d_in[4];
    float* out = (float*)d_out;

    static int inited = 0;
    if (!inited) {
        cudaFuncSetAttribute(gemm_bf16,
            cudaFuncAttributeMaxDynamicSharedMemorySize, GEMM_SMEM);
        cudaFuncSetAttribute(attn_bf16,
            cudaFuncAttributeMaxDynamicSharedMemorySize, ATTN_SMEM_BYTES);
        inited = 1;
    }

    // resolve device symbol addresses on host side via cudaGetSymbolAddress?
    // Not needed: kernels reference the globals directly.

    // 0) convert inputs to bf16 hi/lo pool
    convert_kernel<<<CVT_TOTAL / 4 / 256, 256>>>(x, Wq, Wk, Wv, Wo);

    // device-symbol pointers for gemm params (same addresses in device code)
    // QKV projections: A = converted x, B = converted weights (z-indexed)
    {
        __nv_bfloat16 *cH, *cL;
        cudaGetSymbolAddress((void**)&cH, g_cvtH);
        cudaGetSymbolAddress((void**)&cL, g_cvtL);
        dim3 gqkv(HIDDEN / 128, MROWS / 128, 3);
        gemm_bf16<<<gqkv, 256, GEMM_SMEM>>>(cH + XOFF, cL + XOFF,
                                            cH + WOFF, cL + WOFF, nullptr, 0);

        // 2) attention
        dim3 gattn(SEQ / 128, BATCH * NHEAD, 1);
        attn_bf16<<<gattn, 256, ATTN_SMEM_BYTES>>>();

        // 3) output projection
        __nv_bfloat16 *oH, *oL;
        cudaGetSymbolAddress((void**)&oH, g_Oh);
        cudaGetSymbolAddress((void**)&oL, g_Ol);
        dim3 gout(HIDDEN / 128, MROWS / 128, 1);
        gemm_bf16<<<gout, 256, GEMM_SMEM>>>(oH, oL,
                                            cH + WOFF + 3 * WSZ, cL + WOFF + 3 * WSZ,
                                            out, 1);
    }
}

// round 6
// speedup vs baseline: 5.0781x; 1.1044x over previous
#include <cuda_runtime.h>
#include <cuda_bf16.h>
#include <stdint.h>
#include <math.h>

#define HIDDEN 1024
#define NHEAD  16
#define SEQ    2048
#define BATCH  2
#define MROWS  (BATCH*SEQ)   // 4096

// converted input pool: [ x (4M) | Wq (1M) | Wk | Wv | Wo ]  (element counts)
#define XOFF 0
#define WOFF (4*1024*1024)
#define WSZ  (1024*1024)
#define CVT_TOTAL (8*1024*1024)

__device__ __nv_bfloat16 g_cvtH[CVT_TOTAL];
__device__ __nv_bfloat16 g_cvtL[CVT_TOTAL];

// Q/K/V in [b,h,s,d] layout, bf16 hi/lo (Q pre-scaled by 0.125)
__device__ __nv_bfloat16 g_Qh[BATCH*NHEAD*SEQ*64], g_Ql[BATCH*NHEAD*SEQ*64];
__device__ __nv_bfloat16 g_Kh[BATCH*NHEAD*SEQ*64], g_Kl[BATCH*NHEAD*SEQ*64];
__device__ __nv_bfloat16 g_Vh[BATCH*NHEAD*SEQ*64], g_Vl[BATCH*NHEAD*SEQ*64];
// attention output, [b,s,1024], bf16 hi/lo
__device__ __nv_bfloat16 g_Oh[MROWS*HIDDEN], g_Ol[MROWS*HIDDEN];

// ---------------------------------------------------------------------------
// helpers
// ---------------------------------------------------------------------------
__device__ __forceinline__ uint32_t smaddr(const void* p) {
    return (uint32_t)__cvta_generic_to_shared(p);
}
__device__ __forceinline__ void cpasync16(uint32_t s, const void* g) {
    asm volatile("cp.async.cg.shared.global [%0], [%1], 16;\n"
        :: "r"(s), "l"(__cvta_generic_to_global(g)));
}
#define CP_COMMIT() asm volatile("cp.async.commit_group;\n")
#define CP_WAIT(n)  asm volatile("cp.async.wait_group %0;\n" :: "n"(n))

__device__ __forceinline__ void ldsm4(uint32_t r[4], uint32_t addr) {
    asm volatile("ldmatrix.sync.aligned.m8n8.x4.shared.b16 {%0,%1,%2,%3},[%4];\n"
        : "=r"(r[0]), "=r"(r[1]), "=r"(r[2]), "=r"(r[3]) : "r"(addr));
}
__device__ __forceinline__ void ldsm4t(uint32_t r[4], uint32_t addr) {
    asm volatile("ldmatrix.sync.aligned.m8n8.x4.trans.shared.b16 {%0,%1,%2,%3},[%4];\n"
        : "=r"(r[0]), "=r"(r[1]), "=r"(r[2]), "=r"(r[3]) : "r"(addr));
}
__device__ __forceinline__ void mmabf(float c[4], const uint32_t a[4], const uint32_t b[2]) {
    asm volatile("mma.sync.aligned.m16n8k16.row.col.f32.bf16.bf16.f32 "
        "{%0,%1,%2,%3},{%4,%5,%6,%7},{%8,%9},{%0,%1,%2,%3};\n"
        : "+f"(c[0]), "+f"(c[1]), "+f"(c[2]), "+f"(c[3])
        : "r"(a[0]), "r"(a[1]), "r"(a[2]), "r"(a[3]), "r"(b[0]), "r"(b[1]));
}

// split a,b into packed bf16x2 hi and lo words; x ~= hi + lo (err ~2^-17)
__device__ __forceinline__ void split2(float a, float b, uint32_t& h, uint32_t& l) {
    __nv_bfloat16 ah = __float2bfloat16(a);
    __nv_bfloat16 bh = __float2bfloat16(b);
    __nv_bfloat16 al = __float2bfloat16(a - __bfloat162float(ah));
    __nv_bfloat16 bl = __float2bfloat16(b - __bfloat162float(bh));
    __nv_bfloat162 hv; hv.x = ah; hv.y = bh;
    __nv_bfloat162 lv; lv.x = al; lv.y = bl;
    h = *reinterpret_cast<uint32_t*>(&hv);
    l = *reinterpret_cast<uint32_t*>(&lv);
}

// swizzled byte offsets (conflict-free for cp.async stores + ldmatrix reads)
__device__ __forceinline__ uint32_t swz64(int row, int c16) {   // 64B rows (32 bf16)
    return (uint32_t)(row * 64 + ((c16 ^ (row & 3)) << 4));
}
__device__ __forceinline__ uint32_t swz128(int row, int c16) {  // 128B rows (64 bf16)
    return (uint32_t)(row * 128 + ((c16 ^ (row & 7)) << 4));
}

// ---------------------------------------------------------------------------
// converter: fp32 -> bf16 hi/lo pool  (x then Wq,Wk,Wv,Wo)
// ---------------------------------------------------------------------------
__global__ __launch_bounds__(256) void convert_kernel(
    const float* __restrict__ x,  const float* __restrict__ wq,
    const float* __restrict__ wk, const float* __restrict__ wv,
    const float* __restrict__ wo)
{
    const size_t idx4 = (size_t)blockIdx.x * blockDim.x + threadIdx.x; // 4 elems each
    const size_t off  = idx4 << 2;
    const float* src;
    if (off < (size_t)WOFF) {
        src = x + off;
    } else {
        const size_t wo_off = off - WOFF;
        const int w = (int)(wo_off >> 20);
        const size_t r = wo_off & (WSZ - 1);
        src = (w == 0 ? wq : w == 1 ? wk : w == 2 ? wv : wo) + r;
    }
    float4 f = *(const float4*)src;
    uint32_t h0, l0, h1, l1;
    split2(f.x, f.y, h0, l0);
    split2(f.z, f.w, h1, l1);
    *(uint2*)(g_cvtH + off) = make_uint2(h0, h1);
    *(uint2*)(g_cvtL + off) = make_uint2(l0, l1);
}

// ---------------------------------------------------------------------------
// GEMM: C[m,n] = sum_k A[m,k]*W[n,k], operands pre-split bf16 hi/lo.
// 128x128 block tile, 512 thr (16 warps, 4x4 grid, warp tile 32x32),
// K-chunk 32, 3-stage cp.async, swizzled smem.
// mode 0: scatter hi/lo to g_Q/K/V [b,h,s,d] (Q scaled 0.125); mode 1: fp32 rows.
// ---------------------------------------------------------------------------
#define GSTAGE 32768                  // bytes per stage: 4 comps x 128x32 bf16
#define GEMM_SMEM (3 * GSTAGE)        // 98304

__global__ __launch_bounds__(512, 1) void gemm_bf16(
    const __nv_bfloat16* __restrict__ Ah_g, const __nv_bfloat16* __restrict__ Al_g,
    const __nv_bfloat16* __restrict__ Bh_g, const __nv_bfloat16* __restrict__ Bl_g,
    float* __restrict__ Cout, int mode)
{
    extern __shared__ char dynsm[];
    const uint32_t smb = smaddr(dynsm);

    const int tid  = threadIdx.x;
    const int lane = tid & 31;
    const int warp = tid >> 5;           // 0..15
    const int gq   = lane >> 2;
    const int t    = lane & 3;
    const int wm   = warp >> 2;          // 0..3
    const int wn   = warp & 3;           // 0..3
    const int brow = blockIdx.y << 7;
    const int bcol = blockIdx.x << 7;
    const int z    = blockIdx.z;

    if (mode == 0) { Bh_g += (size_t)z << 20; Bl_g += (size_t)z << 20; }

    // per-thread copy: row cr (0..127), one 16B chunk cc (0..3) per array
    const int cr = tid >> 2;
    const int cc = tid & 3;
    const char* gAh = (const char*)(Ah_g + (size_t)(brow + cr) * HIDDEN);
    const char* gAl = (const char*)(Al_g + (size_t)(brow + cr) * HIDDEN);
    const char* gBh = (const char*)(Bh_g + (size_t)(bcol + cr) * HIDDEN);
    const char* gBl = (const char*)(Bl_g + (size_t)(bcol + cr) * HIDDEN);
    const uint32_t sw0 = swz64(cr, cc);

    #define GCOPY(S, KC) do {                                            \
        uint32_t sb_ = smb + (S) * GSTAGE;                               \
        size_t go_ = (size_t)(KC) * 64 + cc * 16;                        \
        cpasync16(sb_ +     0 + sw0, gAh + go_);                         \
        cpasync16(sb_ +  8192 + sw0, gAl + go_);                         \
        cpasync16(sb_ + 16384 + sw0, gBh + go_);                         \
        cpasync16(sb_ + 24576 + sw0, gBl + go_);                         \
    } while (0)

    float acc[2][4][4];
    #pragma unroll
    for (int i = 0; i < 2; i++)
        #pragma unroll
        for (int j = 0; j < 4; j++)
            #pragma unroll
            for (int k = 0; k < 4; k++) acc[i][j][k] = 0.f;

    GCOPY(0, 0); CP_COMMIT();
    GCOPY(1, 1); CP_COMMIT();

    int st = 0, stn = 2;
    for (int kc = 0; kc < 32; kc++) {
        if (kc == 31) { CP_WAIT(0); } else { CP_WAIT(1); }
        __syncthreads();
        if (kc + 2 < 32) {
            GCOPY(stn, kc + 2); CP_COMMIT();
        }
        const uint32_t sb = smb + st * GSTAGE;
        #pragma unroll
        for (int ks = 0; ks < 2; ks++) {
            uint32_t aH[2][4], aL[2][4], bH[8], bL[8];
            #pragma unroll
            for (int mi = 0; mi < 2; mi++) {
                int row = wm * 32 + mi * 16 + (lane & 15);
                int c16 = ks * 2 + (lane >> 4);
                uint32_t ad = sb + swz64(row, c16);
                ldsm4(aH[mi], ad);
                ldsm4(aL[mi], ad + 8192);
            }
            #pragma unroll
            for (int p = 0; p < 2; p++) {
                int row = wn * 32 + p * 16 + (lane & 7) + ((lane >> 4) & 1) * 8;
                int c16 = ks * 2 + ((lane >> 3) & 1);
                uint32_t bd = sb + 16384 + swz64(row, c16);
                ldsm4(&bH[p * 4], bd);
                ldsm4(&bL[p * 4], bd + 8192);
            }
            #pragma unroll
            for (int mi = 0; mi < 2; mi++)
                #pragma unroll
                for (int ni = 0; ni < 4; ni++) {
                    mmabf(acc[mi][ni], aH[mi], &bH[ni * 2]);
                    mmabf(acc[mi][ni], aH[mi], &bL[ni * 2]);
                    mmabf(acc[mi][ni], aL[mi], &bH[ni * 2]);
                }
        }
        __syncthreads();
        st = (st == 2) ? 0 : st + 1;
        stn = (stn == 2) ? 0 : stn + 1;
    }
    #undef GCOPY

    // epilogue
    const float scale = (mode == 0 && z == 0) ? 0.125f : 1.0f;
    __nv_bfloat16* dh = (z == 0) ? g_Qh : (z == 1) ? g_Kh : g_Vh;
    __nv_bfloat16* dl = (z == 0) ? g_Ql : (z == 1) ? g_Kl : g_Vl;
    #pragma unroll
    for (int mi = 0; mi < 2; mi++)
        #pragma unroll
        for (int ni = 0; ni < 4; ni++) {
            int m0 = brow + wm * 32 + mi * 16 + gq;
            int n0 = bcol + wn * 32 + ni * 8 + 2 * t;
            if (mode == 0) {
                int b = m0 >> 11, s = m0 & 2047;
                int hd = n0 >> 6, d = n0 & 63;
                size_t e0 = (((size_t)(b * NHEAD + hd) * SEQ + s) << 6) + d;
                size_t e1 = (((size_t)(b * NHEAD + hd) * SEQ + (s + 8)) << 6) + d;
                uint32_t uh, ul;
                split2(acc[mi][ni][0] * scale, acc[mi][ni][1] * scale, uh, ul);
                *(uint32_t*)&dh[e0] = uh; *(uint32_t*)&dl[e0] = ul;
                split2(acc[mi][ni][2] * scale, acc[mi][ni][3] * scale, uh, ul);
                *(uint32_t*)&dh[e1] = uh; *(uint32_t*)&dl[e1] = ul;
            } else {
                *(float2*)&Cout[(size_t)m0 * HIDDEN + n0] =
                    make_float2(acc[mi][ni][0], acc[mi][ni][1]);
                *(float2*)&Cout[(size_t)(m0 + 8) * HIDDEN + n0] =
                    make_float2(acc[mi][ni][2], acc[mi][ni][3]);
            }
        }
}

// ---------------------------------------------------------------------------
// Flash attention: 256 q-rows/block (16 warps x 16 rows), 64-key tiles,
// K/V double-buffered cp.async.
// smem (bytes): Qh 0, Ql 32K, Ph 64K, Pl 96K, KV stage s at 128K + 32K*s
//   (stage: Kh 8K | Kl 8K | Vh 8K | Vl 8K).  Total 192K.
// ---------------------------------------------------------------------------
#define ATTN_SMEM_BYTES 196608
#define A_QL 32768
#define A_PH 65536
#define A_PL 98304
#define KVB(s) (131072 + (s) * 32768)

__global__ __launch_bounds__(512, 1) void attn_bf16()
{
    extern __shared__ char dynsm[];
    const uint32_t smb = smaddr(dynsm);

    const int tid  = threadIdx.x;
    const int lane = tid & 31;
    const int warp = tid >> 5;           // 0..15 -> q rows warp*16..+15
    const int gq   = lane >> 2;
    const int t    = lane & 3;
    const int qt   = blockIdx.x;         // 0..7 (256 rows each)
    const int bh   = blockIdx.y;         // 0..31

    const size_t hb = (size_t)bh << 17;

    // ---- Q tile copy (pre-scaled hi/lo bf16 in gmem) ----
    {
        const int row = tid >> 1;                 // 0..255
        const int cb  = (tid & 1) << 2;
        const char* gqh = (const char*)(g_Qh + hb + ((size_t)qt << 14) + row * 64);
        const char* gql = (const char*)(g_Ql + hb + ((size_t)qt << 14) + row * 64);
        #pragma unroll
        for (int i = 0; i < 4; i++) {
            int c16 = cb + i;
            uint32_t sw = swz128(row, c16);
            cpasync16(smb + sw,        gqh + c16 * 16);
            cpasync16(smb + A_QL + sw, gql + c16 * 16);
        }
    }

    // per-thread K/V copy: row kvr (0..63), one chunk kvc (0..7) per array
    const int kvr = tid >> 3;
    const int kvc = tid & 7;
    const char* gkh = (const char*)(g_Kh + hb + kvr * 64) + kvc * 16;
    const char* gkl = (const char*)(g_Kl + hb + kvr * 64) + kvc * 16;
    const char* gvh = (const char*)(g_Vh + hb + kvr * 64) + kvc * 16;
    const char* gvl = (const char*)(g_Vl + hb + kvr * 64) + kvc * 16;
    const uint32_t ksw = swz128(kvr, kvc);

    #define KVCOPY(S, KT) do {                                           \
        uint32_t sb_ = smb + KVB(S);                                     \
        size_t go_ = (size_t)(KT) * 8192;                                \
        cpasync16(sb_ +     0 + ksw, gkh + go_);                         \
        cpasync16(sb_ +  8192 + ksw, gkl + go_);                         \
        cpasync16(sb_ + 16384 + ksw, gvh + go_);                         \
        cpasync16(sb_ + 24576 + ksw, gvl + go_);                         \
    } while (0)

    float m0 = -1e30f, m1 = -1e30f, l0 = 0.f, l1 = 0.f;
    float accO[8][4];
    #pragma unroll
    for (int i = 0; i < 8; i++)
        #pragma unroll
        for (int j = 0; j < 4; j++) accO[i][j] = 0.f;

    KVCOPY(0, 0); CP_COMMIT();

    for (int kt = 0; kt < 32; kt++) {
        CP_WAIT(0);
        __syncthreads();
        if (kt + 1 < 32) { KVCOPY((kt + 1) & 1, kt + 1); CP_COMMIT(); }
        const uint32_t kvb = smb + KVB(kt & 1);

        // ---- S = Q K^T ----
        float accS[8][4];
        #pragma unroll
        for (int i = 0; i < 8; i++)
            #pragma unroll
            for (int j = 0; j < 4; j++) accS[i][j] = 0.f;

        #pragma unroll
        for (int c = 0; c < 4; c++) {
            uint32_t aH[4], aL[4], bH[16], bL[16];
            {
                int row = warp * 16 + (lane & 15);
                int c16 = c * 2 + (lane >> 4);
                uint32_t ad = smb + swz128(row, c16);
                ldsm4(aH, ad);
                ldsm4(aL, ad + A_QL);
            }
            #pragma unroll
            for (int p = 0; p < 4; p++) {
                int row = p * 16 + (lane & 7) + ((lane >> 4) & 1) * 8;
                int c16 = c * 2 + ((lane >> 3) & 1);
                uint32_t bd = kvb + swz128(row, c16);
                ldsm4(&bH[p * 4], bd);
                ldsm4(&bL[p * 4], bd + 8192);
            }
            #pragma unroll
            for (int nt = 0; nt < 8; nt++) {
                mmabf(accS[nt], aH, &bH[nt * 2]);
                mmabf(accS[nt], aH, &bL[nt * 2]);
                mmabf(accS[nt], aL, &bH[nt * 2]);
            }
        }

        // ---- online softmax ----
        float mx0 = accS[0][0], mx1 = accS[0][2];
        #pragma unroll
        for (int nt = 0; nt < 8; nt++) {
            mx0 = fmaxf(mx0, fmaxf(accS[nt][0], accS[nt][1]));
            mx1 = fmaxf(mx1, fmaxf(accS[nt][2], accS[nt][3]));
        }
        mx0 = fmaxf(mx0, __shfl_xor_sync(0xffffffffu, mx0, 1));
        mx0 = fmaxf(mx0, __shfl_xor_sync(0xffffffffu, mx0, 2));
        mx1 = fmaxf(mx1, __shfl_xor_sync(0xffffffffu, mx1, 1));
        mx1 = fmaxf(mx1, __shfl_xor_sync(0xffffffffu, mx1, 2));
        const float nm0 = fmaxf(m0, mx0), nm1 = fmaxf(m1, mx1);
        const float cr0 = __expf(m0 - nm0), cr1 = __expf(m1 - nm1);
        float s0 = 0.f, s1 = 0.f;
        #pragma unroll
        for (int nt = 0; nt < 8; nt++) {
            accS[nt][0] = __expf(accS[nt][0] - nm0); s0 += accS[nt][0];
            accS[nt][1] = __expf(accS[nt][1] - nm0); s0 += accS[nt][1];
            accS[nt][2] = __expf(accS[nt][2] - nm1); s1 += accS[nt][2];
            accS[nt][3] = __expf(accS[nt][3] - nm1); s1 += accS[nt][3];
        }
        s0 += __shfl_xor_sync(0xffffffffu, s0, 1);
        s0 += __shfl_xor_sync(0xffffffffu, s0, 2);
        s1 += __shfl_xor_sync(0xffffffffu, s1, 1);
        s1 += __shfl_xor_sync(0xffffffffu, s1, 2);
        l0 = l0 * cr0 + s0;  l1 = l1 * cr1 + s1;
        m0 = nm0;  m1 = nm1;
        #pragma unroll
        for (int nt = 0; nt < 8; nt++) {
            accO[nt][0] *= cr0; accO[nt][1] *= cr0;
            accO[nt][2] *= cr1; accO[nt][3] *= cr1;
        }

        // ---- stage P (warp-private rows) as hi/lo ----
        __syncwarp();
        {
            const int r0 = warp * 16 + gq;
            const int r1 = r0 + 8;
            #pragma unroll
            for (int nt = 0; nt < 8; nt++) {
                uint32_t ph0 = smb + A_PH + r0 * 128 + ((nt ^ (r0 & 7)) << 4) + 4 * t;
                uint32_t ph1 = smb + A_PH + r1 * 128 + ((nt ^ (r1 & 7)) << 4) + 4 * t;
                uint32_t h, l;
                split2(accS[nt][0], accS[nt][1], h, l);
                asm volatile("st.shared.b32 [%0], %1;\n" :: "r"(ph0), "r"(h));
                asm volatile("st.shared.b32 [%0], %1;\n" :: "r"(ph0 + 32768), "r"(l));
                split2(accS[nt][2], accS[nt][3], h, l);
                asm volatile("st.shared.b32 [%0], %1;\n" :: "r"(ph1), "r"(h));
                asm volatile("st.shared.b32 [%0], %1;\n" :: "r"(ph1 + 32768), "r"(l));
            }
        }
        __syncwarp();

        // ---- O += P V ----
        #pragma unroll
        for (int c = 0; c < 4; c++) {
            uint32_t aH[4], aL[4], bH[16], bL[16];
            {
                int row = warp * 16 + (lane & 15);
                int c16 = c * 2 + (lane >> 4);
                uint32_t ad = smb + A_PH + swz128(row, c16);
                ldsm4(aH, ad);
                ldsm4(aL, ad + 32768);
            }
            #pragma unroll
            for (int p = 0; p < 4; p++) {
                int row = c * 16 + (lane & 15);
                int c16 = p * 2 + (lane >> 4);
                uint32_t vd = kvb + 16384 + swz128(row, c16);
                ldsm4t(&bH[p * 4], vd);
                ldsm4t(&bL[p * 4], vd + 8192);
            }
            #pragma unroll
            for (int nt = 0; nt < 8; nt++) {
                mmabf(accO[nt], aH, &bH[nt * 2]);
                mmabf(accO[nt], aH, &bL[nt * 2]);
                mmabf(accO[nt], aL, &bH[nt * 2]);
            }
        }
        __syncthreads();
    }
    #undef KVCOPY

    // ---- epilogue: normalize, split, write g_Oh/g_Ol [b,s,1024] ----
    const float i0 = 1.f / l0, i1 = 1.f / l1;
    const int sg = qt * 256 + warp * 16 + gq;
    const int b = bh >> 4, hh = bh & 15;
    #pragma unroll
    for (int nt = 0; nt < 8; nt++) {
        size_t e0 = (size_t)(b * SEQ + sg) * HIDDEN + hh * 64 + nt * 8 + 2 * t;
        size_t e1 = e0 + (size_t)8 * HIDDEN;
        uint32_t h, l;
        split2(accO[nt][0] * i0, accO[nt][1] * i0, h, l);
        *(uint32_t*)&g_Oh[e0] = h; *(uint32_t*)&g_Ol[e0] = l;
        split2(accO[nt][2] * i1, accO[nt][3] * i1, h, l);
        *(uint32_t*)&g_Oh[e1] = h; *(uint32_t*)&g_Ol[e1] = l;
    }
}

// ---------------------------------------------------------------------------
extern "C" void kernel_launch(void* const* d_in, const int* in_sizes, int n_in,
                              void* d_out, int out_size)
{
    const float* x  = (const float*)d_in[0];
    const float* Wq = (const float*)d_in[1];
    const float* Wk = (const float*)d_in[2];
    const float* Wv = (const float*)d_in[3];
    const float* Wo = (const float*)d_in[4];
    float* out = (float*)d_out;

    static int inited = 0;
    if (!inited) {
        cudaFuncSetAttribute(gemm_bf16,
            cudaFuncAttributeMaxDynamicSharedMemorySize, GEMM_SMEM);
        cudaFuncSetAttribute(attn_bf16,
            cudaFuncAttributeMaxDynamicSharedMemorySize, ATTN_SMEM_BYTES);
        inited = 1;
    }

    // 0) convert inputs to bf16 hi/lo pool
    convert_kernel<<<CVT_TOTAL / 4 / 256, 256>>>(x, Wq, Wk, Wv, Wo);

    {
        __nv_bfloat16 *cH, *cL;
        cudaGetSymbolAddress((void**)&cH, g_cvtH);
        cudaGetSymbolAddress((void**)&cL, g_cvtL);

        // 1) Q,K,V projections
        dim3 gqkv(HIDDEN / 128, MROWS / 128, 3);
        gemm_bf16<<<gqkv, 512, GEMM_SMEM>>>(cH + XOFF, cL + XOFF,
                                            cH + WOFF, cL + WOFF, nullptr, 0);

        // 2) fused flash attention -> g_Oh/g_Ol
        dim3 gattn(SEQ / 256, BATCH * NHEAD, 1);
        attn_bf16<<<gattn, 512, ATTN_SMEM_BYTES>>>();

        // 3) output projection -> d_out
        __nv_bfloat16 *oH, *oL;
        cudaGetSymbolAddress((void**)&oH, g_Oh);
        cudaGetSymbolAddress((void**)&oL, g_Ol);
        dim3 gout(HIDDEN / 128, MROWS / 128, 1);
        gemm_bf16<<<gout, 512, GEMM_SMEM>>>(oH, oL,
                                            cH + WOFF + 3 * WSZ, cL + WOFF + 3 * WSZ,
                                            out, 1);
    }
}

// round 9
// speedup vs baseline: 6.1110x; 1.2034x over previous
#include <cuda_runtime.h>
#include <cuda_bf16.h>
#include <stdint.h>
#include <math.h>

#define HIDDEN 1024
#define NHEAD  16
#define SEQ    2048
#define BATCH  2
#define MROWS  (BATCH*SEQ)   // 4096

// Q pre-scale: 1/sqrt(64) * log2(e)  (attention uses exp2)
#define QSCALE 0.1803368801111244f

// converted input pool: [ x (4M) | Wq (1M) | Wk | Wv | Wo ]  (element counts)
#define XOFF 0
#define WOFF (4*1024*1024)
#define WSZ  (1024*1024)
#define CVT_TOTAL (8*1024*1024)

__device__ __nv_bfloat16 g_cvtH[CVT_TOTAL];
__device__ __nv_bfloat16 g_cvtL[CVT_TOTAL];

// Q/K/V in [b,h,s,d] layout, bf16 hi/lo (Q pre-scaled by QSCALE)
__device__ __nv_bfloat16 g_Qh[BATCH*NHEAD*SEQ*64], g_Ql[BATCH*NHEAD*SEQ*64];
__device__ __nv_bfloat16 g_Kh[BATCH*NHEAD*SEQ*64], g_Kl[BATCH*NHEAD*SEQ*64];
__device__ __nv_bfloat16 g_Vh[BATCH*NHEAD*SEQ*64], g_Vl[BATCH*NHEAD*SEQ*64];
// attention output, [b,s,1024], bf16 hi/lo
__device__ __nv_bfloat16 g_Oh[MROWS*HIDDEN], g_Ol[MROWS*HIDDEN];

// ---------------------------------------------------------------------------
// helpers
// ---------------------------------------------------------------------------
__device__ __forceinline__ uint32_t smaddr(const void* p) {
    return (uint32_t)__cvta_generic_to_shared(p);
}
__device__ __forceinline__ void cpasync16(uint32_t s, const void* g) {
    asm volatile("cp.async.cg.shared.global [%0], [%1], 16;\n"
        :: "r"(s), "l"(__cvta_generic_to_global(g)));
}
#define CP_COMMIT() asm volatile("cp.async.commit_group;\n")
#define CP_WAIT(n)  asm volatile("cp.async.wait_group %0;\n" :: "n"(n))

__device__ __forceinline__ void ldsm4(uint32_t r[4], uint32_t addr) {
    asm volatile("ldmatrix.sync.aligned.m8n8.x4.shared.b16 {%0,%1,%2,%3},[%4];\n"
        : "=r"(r[0]), "=r"(r[1]), "=r"(r[2]), "=r"(r[3]) : "r"(addr));
}
__device__ __forceinline__ void ldsm4t(uint32_t r[4], uint32_t addr) {
    asm volatile("ldmatrix.sync.aligned.m8n8.x4.trans.shared.b16 {%0,%1,%2,%3},[%4];\n"
        : "=r"(r[0]), "=r"(r[1]), "=r"(r[2]), "=r"(r[3]) : "r"(addr));
}
__device__ __forceinline__ void mmabf(float c[4], const uint32_t a[4], const uint32_t b[2]) {
    asm volatile("mma.sync.aligned.m16n8k16.row.col.f32.bf16.bf16.f32 "
        "{%0,%1,%2,%3},{%4,%5,%6,%7},{%8,%9},{%0,%1,%2,%3};\n"
        : "+f"(c[0]), "+f"(c[1]), "+f"(c[2]), "+f"(c[3])
        : "r"(a[0]), "r"(a[1]), "r"(a[2]), "r"(a[3]), "r"(b[0]), "r"(b[1]));
}
__device__ __forceinline__ float ex2(float x) {
    float y;
    asm("ex2.approx.f32 %0, %1;" : "=f"(y) : "f"(x));
    return y;
}

// split a,b into packed bf16x2 hi and lo words; x ~= hi + lo (err ~2^-17)
__device__ __forceinline__ void split2(float a, float b, uint32_t& h, uint32_t& l) {
    __nv_bfloat16 ah = __float2bfloat16(a);
    __nv_bfloat16 bh = __float2bfloat16(b);
    __nv_bfloat16 al = __float2bfloat16(a - __bfloat162float(ah));
    __nv_bfloat16 bl = __float2bfloat16(b - __bfloat162float(bh));
    __nv_bfloat162 hv; hv.x = ah; hv.y = bh;
    __nv_bfloat162 lv; lv.x = al; lv.y = bl;
    h = *reinterpret_cast<uint32_t*>(&hv);
    l = *reinterpret_cast<uint32_t*>(&lv);
}

// swizzled byte offsets (conflict-free cp.async stores + ldmatrix reads)
__device__ __forceinline__ uint32_t swz64(int row, int c16) {   // 64B rows
    return (uint32_t)(row * 64 + ((c16 ^ (row & 3)) << 4));
}
__device__ __forceinline__ uint32_t swz128(int row, int c16) {  // 128B rows
    return (uint32_t)(row * 128 + ((c16 ^ (row & 7)) << 4));
}

// ---------------------------------------------------------------------------
// converter: fp32 -> bf16 hi/lo pool  (x then Wq,Wk,Wv,Wo)
// ---------------------------------------------------------------------------
__global__ __launch_bounds__(256) void convert_kernel(
    const float* __restrict__ x,  const float* __restrict__ wq,
    const float* __restrict__ wk, const float* __restrict__ wv,
    const float* __restrict__ wo)
{
    const size_t idx4 = (size_t)blockIdx.x * blockDim.x + threadIdx.x;
    const size_t off  = idx4 << 2;
    const float* src;
    if (off < (size_t)WOFF) {
        src = x + off;
    } else {
        const size_t wo_off = off - WOFF;
        const int w = (int)(wo_off >> 20);
        const size_t r = wo_off & (WSZ - 1);
        src = (w == 0 ? wq : w == 1 ? wk : w == 2 ? wv : wo) + r;
    }
    float4 f = *(const float4*)src;
    uint32_t h0, l0, h1, l1;
    split2(f.x, f.y, h0, l0);
    split2(f.z, f.w, h1, l1);
    *(uint2*)(g_cvtH + off) = make_uint2(h0, h1);
    *(uint2*)(g_cvtL + off) = make_uint2(l0, l1);
}

// ---------------------------------------------------------------------------
// GEMM: C[m,n] = sum_k A[m,k]*W[n,k], pre-split bf16 hi/lo, 3-term mma.
// Block tile 128x256, 256 thr (8 warps 2x4), warp tile 64x64, K-chunk 32,
// 3-stage cp.async pipeline, swizzled smem (64B rows).
// Stage (48KB): Ah 0 | Al 8K | Bh 16K | Bl 32K.
// mode 0: scatter hi/lo to g_Q/K/V [b,h,s,d] (Q scaled QSCALE); mode 1: fp32.
// ---------------------------------------------------------------------------
#define G_STAGE 49152
#define G_SMEM  (3 * G_STAGE)   // 147456

__global__ __launch_bounds__(256, 1) void gemm_bf16(
    const __nv_bfloat16* __restrict__ Ah_g, const __nv_bfloat16* __restrict__ Al_g,
    const __nv_bfloat16* __restrict__ Bh_g, const __nv_bfloat16* __restrict__ Bl_g,
    float* __restrict__ Cout, int mode)
{
    extern __shared__ char dynsm[];
    const uint32_t smb = smaddr(dynsm);

    const int tid  = threadIdx.x;
    const int lane = tid & 31;
    const int warp = tid >> 5;           // 0..7
    const int gq   = lane >> 2;
    const int t    = lane & 3;
    const int wm   = warp >> 2;          // 0..1  (64-row block)
    const int wn   = warp & 3;           // 0..3  (64-col block)
    const int brow = blockIdx.y << 7;
    const int bcol = blockIdx.x << 8;
    const int z    = blockIdx.z;

    if (mode == 0) { Bh_g += (size_t)z << 20; Bl_g += (size_t)z << 20; }

    const char* gAh = (const char*)(Ah_g + (size_t)brow * HIDDEN);
    const char* gAl = (const char*)(Al_g + (size_t)brow * HIDDEN);
    const char* gBh = (const char*)(Bh_g + (size_t)bcol * HIDDEN);
    const char* gBl = (const char*)(Bl_g + (size_t)bcol * HIDDEN);

    // copy: 3072 16B chunks/stage over 256 thr = 12 each
    // t 0-1: Ah (512 chunks), 2-3: Al, 4-7: Bh (1024), 8-11: Bl
    #define GCOPY(S, KC) do {                                                 \
        const uint32_t stb_ = smb + (S) * G_STAGE;                            \
        const size_t go_ = (size_t)(KC) * 64;                                 \
        _Pragma("unroll")                                                     \
        for (int j_ = 0; j_ < 2; j_++) {                                      \
            int cid_ = j_ * 256 + tid, row_ = cid_ >> 2, c_ = cid_ & 3;       \
            cpasync16(stb_ + swz64(row_, c_),                                 \
                      gAh + (size_t)row_ * 2048 + go_ + c_ * 16);             \
            cpasync16(stb_ + 8192 + swz64(row_, c_),                          \
                      gAl + (size_t)row_ * 2048 + go_ + c_ * 16);             \
        }                                                                     \
        _Pragma("unroll")                                                     \
        for (int j_ = 0; j_ < 4; j_++) {                                      \
            int cid_ = j_ * 256 + tid, row_ = cid_ >> 2, c_ = cid_ & 3;       \
            cpasync16(stb_ + 16384 + swz64(row_, c_),                         \
                      gBh + (size_t)row_ * 2048 + go_ + c_ * 16);             \
            cpasync16(stb_ + 32768 + swz64(row_, c_),                         \
                      gBl + (size_t)row_ * 2048 + go_ + c_ * 16);             \
        }                                                                     \
    } while (0)

    float acc[4][8][4];
    #pragma unroll
    for (int i = 0; i < 4; i++)
        #pragma unroll
        for (int j = 0; j < 8; j++)
            #pragma unroll
            for (int k = 0; k < 4; k++) acc[i][j][k] = 0.f;

    GCOPY(0, 0); CP_COMMIT();
    GCOPY(1, 1); CP_COMMIT();

    int st = 0, stn = 2;
    for (int kc = 0; kc < 32; kc++) {
        if (kc == 31) { CP_WAIT(0); } else { CP_WAIT(1); }
        __syncthreads();
        if (kc + 2 < 32) { GCOPY(stn, kc + 2); CP_COMMIT(); }
        const uint32_t sb = smb + st * G_STAGE;

        #pragma unroll
        for (int ks = 0; ks < 2; ks++) {
            uint32_t aH[4][4], aL[4][4];
            #pragma unroll
            for (int mi = 0; mi < 4; mi++) {
                uint32_t ad = sb + swz64(wm * 64 + mi * 16 + (lane & 15),
                                         ks * 2 + (lane >> 4));
                ldsm4(aH[mi], ad);
                ldsm4(aL[mi], ad + 8192);
            }
            #pragma unroll
            for (int p = 0; p < 4; p++) {
                uint32_t bh4[4], bl4[4];
                uint32_t bd = sb + 16384 +
                    swz64(wn * 64 + p * 16 + (lane & 7) + ((lane >> 4) & 1) * 8,
                          ks * 2 + ((lane >> 3) & 1));
                ldsm4(bh4, bd);
                ldsm4(bl4, bd + 16384);
                #pragma unroll
                for (int mi = 0; mi < 4; mi++)
                    #pragma unroll
                    for (int h = 0; h < 2; h++) {
                        mmabf(acc[mi][2 * p + h], aH[mi], &bh4[h * 2]);
                        mmabf(acc[mi][2 * p + h], aH[mi], &bl4[h * 2]);
                        mmabf(acc[mi][2 * p + h], aL[mi], &bh4[h * 2]);
                    }
            }
        }
        __syncthreads();
        st = (st == 2) ? 0 : st + 1;
        stn = (stn == 2) ? 0 : stn + 1;
    }
    #undef GCOPY

    // epilogue
    const float scale = (mode == 0 && z == 0) ? QSCALE : 1.0f;
    __nv_bfloat16* dh = (z == 0) ? g_Qh : (z == 1) ? g_Kh : g_Vh;
    __nv_bfloat16* dl = (z == 0) ? g_Ql : (z == 1) ? g_Kl : g_Vl;
    #pragma unroll
    for (int mi = 0; mi < 4; mi++)
        #pragma unroll
        for (int ni = 0; ni < 8; ni++) {
            int m0 = brow + wm * 64 + mi * 16 + gq;
            int n0 = bcol + wn * 64 + ni * 8 + 2 * t;
            if (mode == 0) {
                int b = m0 >> 11, s = m0 & 2047;
                int hd = n0 >> 6, d = n0 & 63;
                size_t e0 = (((size_t)(b * NHEAD + hd) * SEQ + s) << 6) + d;
                size_t e1 = (((size_t)(b * NHEAD + hd) * SEQ + (s + 8)) << 6) + d;
                uint32_t uh, ul;
                split2(acc[mi][ni][0] * scale, acc[mi][ni][1] * scale, uh, ul);
                *(uint32_t*)&dh[e0] = uh; *(uint32_t*)&dl[e0] = ul;
                split2(acc[mi][ni][2] * scale, acc[mi][ni][3] * scale, uh, ul);
                *(uint32_t*)&dh[e1] = uh; *(uint32_t*)&dl[e1] = ul;
            } else {
                *(float2*)&Cout[(size_t)m0 * HIDDEN + n0] =
                    make_float2(acc[mi][ni][0], acc[mi][ni][1]);
                *(float2*)&Cout[(size_t)(m0 + 8) * HIDDEN + n0] =
                    make_float2(acc[mi][ni][2], acc[mi][ni][3]);
            }
        }
}

// ---------------------------------------------------------------------------
// Flash attention v3: 256 q-rows/block, 8 warps x 32 rows, 64-key tiles.
// Q fragments cached in registers for all 32 tiles; P packed to bf16 hi/lo
// in registers (mma C layout == next mma A layout); no-max exp2 softmax
// (log2e folded into Q scale).  K/V double-buffered cp.async.
// smem: Qh 0 (32K), Ql 32K, KV stage s at 64K + s*32K:
//       Kh 0 | Kl 8K | Vh 16K | Vl 24K.   Total 128K.
// ---------------------------------------------------------------------------
#define A_SMEM 131072
#define A_KVB(s) (65536 + (s) * 32768)

__global__ __launch_bounds__(256, 1) void attn_bf16()
{
    extern __shared__ char dynsm[];
    const uint32_t smb = smaddr(dynsm);

    const int tid  = threadIdx.x;
    const int lane = tid & 31;
    const int warp = tid >> 5;           // 0..7, rows warp*32..+31
    const int gq   = lane >> 2;
    const int t    = lane & 3;
    const int qt   = blockIdx.x;         // 0..7 (256 rows each)
    const int bh   = blockIdx.y;         // 0..31

    const size_t hb = (size_t)bh << 17;

    // ---- Q tile copy: 256 rows x 128B per component ----
    {
        const char* gqh = (const char*)(g_Qh + hb + ((size_t)qt << 14)) + (size_t)tid * 128;
        const char* gql = (const char*)(g_Ql + hb + ((size_t)qt << 14)) + (size_t)tid * 128;
        #pragma unroll
        for (int i = 0; i < 8; i++) {
            uint32_t sw = swz128(tid, i);
            cpasync16(smb + sw,         gqh + i * 16);
            cpasync16(smb + 32768 + sw, gql + i * 16);
        }
    }
    CP_COMMIT();

    // per-thread K/V copy: row kvr (0..63), chunks kvc, kvc+1 per component
    const int kvr = tid >> 2;
    const int kvc = (tid & 3) << 1;
    const char* gkh = (const char*)(g_Kh + hb) + kvr * 128;
    const char* gkl = (const char*)(g_Kl + hb) + kvr * 128;
    const char* gvh = (const char*)(g_Vh + hb) + kvr * 128;
    const char* gvl = (const char*)(g_Vl + hb) + kvr * 128;
    const uint32_t ksw0 = swz128(kvr, kvc), ksw1 = swz128(kvr, kvc + 1);

    #define KVCOPY(S, KT) do {                                           \
        uint32_t sb_ = smb + A_KVB(S);                                   \
        size_t go_ = (size_t)(KT) * 8192;                                \
        cpasync16(sb_ +     0 + ksw0, gkh + go_ + kvc * 16);             \
        cpasync16(sb_ +  8192 + ksw0, gkl + go_ + kvc * 16);             \
        cpasync16(sb_ + 16384 + ksw0, gvh + go_ + kvc * 16);             \
        cpasync16(sb_ + 24576 + ksw0, gvl + go_ + kvc * 16);             \
        cpasync16(sb_ +     0 + ksw1, gkh + go_ + kvc * 16 + 16);        \
        cpasync16(sb_ +  8192 + ksw1, gkl + go_ + kvc * 16 + 16);        \
        cpasync16(sb_ + 16384 + ksw1, gvh + go_ + kvc * 16 + 16);        \
        cpasync16(sb_ + 24576 + ksw1, gvl + go_ + kvc * 16 + 16);        \
    } while (0)

    KVCOPY(0, 0); CP_COMMIT();
    CP_WAIT(0);
    __syncthreads();

    // ---- cache Q fragments (this warp's 32 rows x 64 cols, hi+lo) ----
    uint32_t qH[2][4][4], qL[2][4][4];
    #pragma unroll
    for (int mb = 0; mb < 2; mb++)
        #pragma unroll
        for (int c = 0; c < 4; c++) {
            uint32_t ad = smb + swz128(warp * 32 + mb * 16 + (lane & 15),
                                       c * 2 + (lane >> 4));
            ldsm4(qH[mb][c], ad);
            ldsm4(qL[mb][c], ad + 32768);
        }

    float accO[2][8][4];
    float lsum[2][2];
    #pragma unroll
    for (int mb = 0; mb < 2; mb++) {
        lsum[mb][0] = 0.f; lsum[mb][1] = 0.f;
        #pragma unroll
        for (int i = 0; i < 8; i++)
            #pragma unroll
            for (int j = 0; j < 4; j++) accO[mb][i][j] = 0.f;
    }

    for (int kt = 0; kt < 32; kt++) {
        CP_WAIT(0);
        __syncthreads();
        if (kt + 1 < 32) { KVCOPY((kt + 1) & 1, kt + 1); CP_COMMIT(); }
        const uint32_t kvb = smb + A_KVB(kt & 1);

        // ---- S = Q K^T  (accS[mb][nt][4], nt = key block of 8) ----
        float accS[2][8][4];
        #pragma unroll
        for (int mb = 0; mb < 2; mb++)
            #pragma unroll
            for (int i = 0; i < 8; i++)
                #pragma unroll
                for (int j = 0; j < 4; j++) accS[mb][i][j] = 0.f;

        #pragma unroll
        for (int c = 0; c < 4; c++)
            #pragma unroll
            for (int p = 0; p < 4; p++) {
                uint32_t kh4[4], kl4[4];
                uint32_t bd = kvb +
                    swz128(p * 16 + (lane & 7) + ((lane >> 4) & 1) * 8,
                           c * 2 + ((lane >> 3) & 1));
                ldsm4(kh4, bd);
                ldsm4(kl4, bd + 8192);
                #pragma unroll
                for (int mb = 0; mb < 2; mb++)
                    #pragma unroll
                    for (int h = 0; h < 2; h++) {
                        mmabf(accS[mb][2 * p + h], qH[mb][c], &kh4[h * 2]);
                        mmabf(accS[mb][2 * p + h], qH[mb][c], &kl4[h * 2]);
                        mmabf(accS[mb][2 * p + h], qL[mb][c], &kh4[h * 2]);
                    }
            }

        // ---- no-max softmax: P = exp2(S); accumulate row sums ----
        #pragma unroll
        for (int mb = 0; mb < 2; mb++) {
            float r0 = 0.f, r1 = 0.f;
            #pragma unroll
            for (int nt = 0; nt < 8; nt++) {
                accS[mb][nt][0] = ex2(accS[mb][nt][0]);
                accS[mb][nt][1] = ex2(accS[mb][nt][1]);
                accS[mb][nt][2] = ex2(accS[mb][nt][2]);
                accS[mb][nt][3] = ex2(accS[mb][nt][3]);
                r0 += accS[mb][nt][0] + accS[mb][nt][1];
                r1 += accS[mb][nt][2] + accS[mb][nt][3];
            }
            r0 += __shfl_xor_sync(0xffffffffu, r0, 1);
            r0 += __shfl_xor_sync(0xffffffffu, r0, 2);
            r1 += __shfl_xor_sync(0xffffffffu, r1, 1);
            r1 += __shfl_xor_sync(0xffffffffu, r1, 2);
            lsum[mb][0] += r0;
            lsum[mb][1] += r1;
        }

        // ---- O += P V  (P fragments packed from accS in registers) ----
        #pragma unroll
        for (int j = 0; j < 4; j++) {
            uint32_t pH[2][4], pL[2][4];
            #pragma unroll
            for (int mb = 0; mb < 2; mb++) {
                split2(accS[mb][2*j][0],   accS[mb][2*j][1],   pH[mb][0], pL[mb][0]);
                split2(accS[mb][2*j][2],   accS[mb][2*j][3],   pH[mb][1], pL[mb][1]);
                split2(accS[mb][2*j+1][0], accS[mb][2*j+1][1], pH[mb][2], pL[mb][2]);
                split2(accS[mb][2*j+1][2], accS[mb][2*j+1][3], pH[mb][3], pL[mb][3]);
            }
            #pragma unroll
            for (int p = 0; p < 4; p++) {
                uint32_t vh4[4], vl4[4];
                uint32_t vd = kvb + 16384 +
                    swz128(j * 16 + (lane & 15), p * 2 + (lane >> 4));
                ldsm4t(vh4, vd);
                ldsm4t(vl4, vd + 8192);
                #pragma unroll
                for (int mb = 0; mb < 2; mb++)
                    #pragma unroll
                    for (int h = 0; h < 2; h++) {
                        mmabf(accO[mb][2 * p + h], pH[mb], &vh4[h * 2]);
                        mmabf(accO[mb][2 * p + h], pH[mb], &vl4[h * 2]);
                        mmabf(accO[mb][2 * p + h], pL[mb], &vh4[h * 2]);
                    }
            }
        }
        __syncthreads();
    }
    #undef KVCOPY

    // ---- epilogue: normalize, split, write g_Oh/g_Ol [b,s,1024] ----
    const int b = bh >> 4, hh = bh & 15;
    #pragma unroll
    for (int mb = 0; mb < 2; mb++) {
        const float i0 = 1.f / lsum[mb][0], i1 = 1.f / lsum[mb][1];
        const int sg = qt * 256 + warp * 32 + mb * 16 + gq;
        #pragma unroll
        for (int nt = 0; nt < 8; nt++) {
            size_t e0 = (size_t)(b * SEQ + sg) * HIDDEN + hh * 64 + nt * 8 + 2 * t;
            size_t e1 = e0 + (size_t)8 * HIDDEN;
            uint32_t h, l;
            split2(accO[mb][nt][0] * i0, accO[mb][nt][1] * i0, h, l);
            *(uint32_t*)&g_Oh[e0] = h; *(uint32_t*)&g_Ol[e0] = l;
            split2(accO[mb][nt][2] * i1, accO[mb][nt][3] * i1, h, l);
            *(uint32_t*)&g_Oh[e1] = h; *(uint32_t*)&g_Ol[e1] = l;
        }
    }
}

// ---------------------------------------------------------------------------
extern "C" void kernel_launch(void* const* d_in, const int* in_sizes, int n_in,
                              void* d_out, int out_size)
{
    const float* x  = (const float*)d_in[0];
    const float* Wq = (const float*)d_in[1];
    const float* Wk = (const float*)d_in[2];
    const float* Wv = (const float*)d_in[3];
    const float* Wo = (const float*)d_in[4];
    float* out = (float*)d_out;

    static int inited = 0;
    if (!inited) {
        cudaFuncSetAttribute(gemm_bf16,
            cudaFuncAttributeMaxDynamicSharedMemorySize, G_SMEM);
        cudaFuncSetAttribute(attn_bf16,
            cudaFuncAttributeMaxDynamicSharedMemorySize, A_SMEM);
        inited = 1;
    }

    // 0) convert inputs to bf16 hi/lo pool
    convert_kernel<<<CVT_TOTAL / 4 / 256, 256>>>(x, Wq, Wk, Wv, Wo);

    {
        __nv_bfloat16 *cH, *cL;
        cudaGetSymbolAddress((void**)&cH, g_cvtH);
        cudaGetSymbolAddress((void**)&cL, g_cvtL);

        // 1) Q,K,V projections
        dim3 gqkv(HIDDEN / 256, MROWS / 128, 3);
        gemm_bf16<<<gqkv, 256, G_SMEM>>>(cH + XOFF, cL + XOFF,
                                         cH + WOFF, cL + WOFF, nullptr, 0);

        // 2) fused flash attention -> g_Oh/g_Ol
        dim3 gattn(SEQ / 256, BATCH * NHEAD, 1);
        attn_bf16<<<gattn, 256, A_SMEM>>>();

        // 3) output projection -> d_out
        __nv_bfloat16 *oH, *oL;
        cudaGetSymbolAddress((void**)&oH, g_Oh);
        cudaGetSymbolAddress((void**)&oL, g_Ol);
        dim3 gout(HIDDEN / 256, MROWS / 128, 1);
        gemm_bf16<<<gout, 256, G_SMEM>>>(oH, oL,
                                         cH + WOFF + 3 * WSZ, cL + WOFF + 3 * WSZ,
                                         out, 1);
    }
}

// round 10
// speedup vs baseline: 6.1722x; 1.0100x over previous
#include <cuda_runtime.h>
#include <cuda_bf16.h>
#include <stdint.h>
#include <math.h>

#define HIDDEN 1024
#define NHEAD  16
#define SEQ    2048
#define BATCH  2
#define MROWS  (BATCH*SEQ)   // 4096

// Q pre-scale: 1/sqrt(64) * log2(e)  (attention uses exp2)
#define QSCALE 0.1803368801111244f

// converted input pool: [ x (4M) | Wq (1M) | Wk | Wv | Wo ]  (element counts)
#define XOFF 0
#define WOFF (4*1024*1024)
#define WSZ  (1024*1024)
#define CVT_TOTAL (8*1024*1024)

__device__ __nv_bfloat16 g_cvtH[CVT_TOTAL];
__device__ __nv_bfloat16 g_cvtL[CVT_TOTAL];

// Q/K/V in [b,h,s,d] layout, bf16 hi/lo (Q pre-scaled by QSCALE)
__device__ __nv_bfloat16 g_Qh[BATCH*NHEAD*SEQ*64], g_Ql[BATCH*NHEAD*SEQ*64];
__device__ __nv_bfloat16 g_Kh[BATCH*NHEAD*SEQ*64], g_Kl[BATCH*NHEAD*SEQ*64];
__device__ __nv_bfloat16 g_Vh[BATCH*NHEAD*SEQ*64], g_Vl[BATCH*NHEAD*SEQ*64];
// attention output, [b,s,1024], bf16 hi/lo
__device__ __nv_bfloat16 g_Oh[MROWS*HIDDEN], g_Ol[MROWS*HIDDEN];

// ---------------------------------------------------------------------------
// helpers
// ---------------------------------------------------------------------------
__device__ __forceinline__ uint32_t smaddr(const void* p) {
    return (uint32_t)__cvta_generic_to_shared(p);
}
__device__ __forceinline__ void cpasync16(uint32_t s, const void* g) {
    asm volatile("cp.async.cg.shared.global [%0], [%1], 16;\n"
        :: "r"(s), "l"(__cvta_generic_to_global(g)));
}
#define CP_COMMIT() asm volatile("cp.async.commit_group;\n")
#define CP_WAIT(n)  asm volatile("cp.async.wait_group %0;\n" :: "n"(n))

__device__ __forceinline__ void ldsm4(uint32_t r[4], uint32_t addr) {
    asm volatile("ldmatrix.sync.aligned.m8n8.x4.shared.b16 {%0,%1,%2,%3},[%4];\n"
        : "=r"(r[0]), "=r"(r[1]), "=r"(r[2]), "=r"(r[3]) : "r"(addr));
}
__device__ __forceinline__ void ldsm4t(uint32_t r[4], uint32_t addr) {
    asm volatile("ldmatrix.sync.aligned.m8n8.x4.trans.shared.b16 {%0,%1,%2,%3},[%4];\n"
        : "=r"(r[0]), "=r"(r[1]), "=r"(r[2]), "=r"(r[3]) : "r"(addr));
}
__device__ __forceinline__ void mmabf(float c[4], const uint32_t a[4], const uint32_t b[2]) {
    asm volatile("mma.sync.aligned.m16n8k16.row.col.f32.bf16.bf16.f32 "
        "{%0,%1,%2,%3},{%4,%5,%6,%7},{%8,%9},{%0,%1,%2,%3};\n"
        : "+f"(c[0]), "+f"(c[1]), "+f"(c[2]), "+f"(c[3])
        : "r"(a[0]), "r"(a[1]), "r"(a[2]), "r"(a[3]), "r"(b[0]), "r"(b[1]));
}
__device__ __forceinline__ float ex2(float x) {
    float y;
    asm("ex2.approx.f32 %0, %1;" : "=f"(y) : "f"(x));
    return y;
}

// split a,b into packed bf16x2 hi and lo words; x ~= hi + lo (err ~2^-17)
__device__ __forceinline__ void split2(float a, float b, uint32_t& h, uint32_t& l) {
    __nv_bfloat16 ah = __float2bfloat16(a);
    __nv_bfloat16 bh = __float2bfloat16(b);
    __nv_bfloat16 al = __float2bfloat16(a - __bfloat162float(ah));
    __nv_bfloat16 bl = __float2bfloat16(b - __bfloat162float(bh));
    __nv_bfloat162 hv; hv.x = ah; hv.y = bh;
    __nv_bfloat162 lv; lv.x = al; lv.y = bl;
    h = *reinterpret_cast<uint32_t*>(&hv);
    l = *reinterpret_cast<uint32_t*>(&lv);
}

// swizzled byte offsets (conflict-free cp.async stores + ldmatrix reads)
__device__ __forceinline__ uint32_t swz64(int row, int c16) {   // 64B rows
    return (uint32_t)(row * 64 + ((c16 ^ (row & 3)) << 4));
}
__device__ __forceinline__ uint32_t swz128(int row, int c16) {  // 128B rows
    return (uint32_t)(row * 128 + ((c16 ^ (row & 7)) << 4));
}

// ---------------------------------------------------------------------------
// converter: fp32 -> bf16 hi/lo pool  (x then Wq,Wk,Wv,Wo)
// ---------------------------------------------------------------------------
__global__ __launch_bounds__(256) void convert_kernel(
    const float* __restrict__ x,  const float* __restrict__ wq,
    const float* __restrict__ wk, const float* __restrict__ wv,
    const float* __restrict__ wo)
{
    const size_t idx4 = (size_t)blockIdx.x * blockDim.x + threadIdx.x;
    const size_t off  = idx4 << 2;
    const float* src;
    if (off < (size_t)WOFF) {
        src = x + off;
    } else {
        const size_t wo_off = off - WOFF;
        const int w = (int)(wo_off >> 20);
        const size_t r = wo_off & (WSZ - 1);
        src = (w == 0 ? wq : w == 1 ? wk : w == 2 ? wv : wo) + r;
    }
    float4 f = *(const float4*)src;
    uint32_t h0, l0, h1, l1;
    split2(f.x, f.y, h0, l0);
    split2(f.z, f.w, h1, l1);
    *(uint2*)(g_cvtH + off) = make_uint2(h0, h1);
    *(uint2*)(g_cvtL + off) = make_uint2(l0, l1);
}

// ---------------------------------------------------------------------------
// GEMM: C[m,n] = sum_k A[m,k]*W[n,k], pre-split bf16 hi/lo, 3-term mma.
// Block tile 128x128, 256 thr (8 warps 2x4), warp tile 64x32, K-chunk 32,
// 3-stage cp.async pipeline, swizzled smem (64B rows), 2 CTAs/SM.
// Split terms are the OUTER mma loop: 16 independent mma between acc reuses.
// Stage (32KB): Ah 0 | Al 8K | Bh 16K | Bl 24K.
// mode 0: scatter hi/lo to g_Q/K/V [b,h,s,d] (Q scaled QSCALE); mode 1: fp32.
// ---------------------------------------------------------------------------
#define G_STAGE 32768
#define G_SMEM  (3 * G_STAGE)   // 98304

__global__ __launch_bounds__(256, 2) void gemm_bf16(
    const __nv_bfloat16* __restrict__ Ah_g, const __nv_bfloat16* __restrict__ Al_g,
    const __nv_bfloat16* __restrict__ Bh_g, const __nv_bfloat16* __restrict__ Bl_g,
    float* __restrict__ Cout, int mode)
{
    extern __shared__ char dynsm[];
    const uint32_t smb = smaddr(dynsm);

    const int tid  = threadIdx.x;
    const int lane = tid & 31;
    const int warp = tid >> 5;           // 0..7
    const int gq   = lane >> 2;
    const int t    = lane & 3;
    const int wm   = warp >> 2;          // 0..1  (64-row block)
    const int wn   = warp & 3;           // 0..3  (32-col block)
    const int brow = blockIdx.y << 7;
    const int bcol = blockIdx.x << 7;
    const int z    = blockIdx.z;

    if (mode == 0) { Bh_g += (size_t)z << 20; Bl_g += (size_t)z << 20; }

    const char* gAh = (const char*)(Ah_g + (size_t)brow * HIDDEN);
    const char* gAl = (const char*)(Al_g + (size_t)brow * HIDDEN);
    const char* gBh = (const char*)(Bh_g + (size_t)bcol * HIDDEN);
    const char* gBl = (const char*)(Bl_g + (size_t)bcol * HIDDEN);

    // copy: 512 chunks x 4 comps / 256 thr = 8 cp.async per thread per stage
    #define GCOPY(S, KC) do {                                                 \
        const uint32_t stb_ = smb + (S) * G_STAGE;                            \
        const size_t go_ = (size_t)(KC) * 64;                                 \
        _Pragma("unroll")                                                     \
        for (int j_ = 0; j_ < 2; j_++) {                                      \
            int cid_ = j_ * 256 + tid, row_ = cid_ >> 2, c_ = cid_ & 3;       \
            uint32_t sw_ = swz64(row_, c_);                                   \
            size_t g_ = (size_t)row_ * 2048 + go_ + c_ * 16;                  \
            cpasync16(stb_ +         sw_, gAh + g_);                          \
            cpasync16(stb_ +  8192 + sw_, gAl + g_);                          \
            cpasync16(stb_ + 16384 + sw_, gBh + g_);                          \
            cpasync16(stb_ + 24576 + sw_, gBl + g_);                          \
        }                                                                     \
    } while (0)

    float acc[4][4][4];
    #pragma unroll
    for (int i = 0; i < 4; i++)
        #pragma unroll
        for (int j = 0; j < 4; j++)
            #pragma unroll
            for (int k = 0; k < 4; k++) acc[i][j][k] = 0.f;

    GCOPY(0, 0); CP_COMMIT();
    GCOPY(1, 1); CP_COMMIT();

    int st = 0, stn = 2;
    for (int kc = 0; kc < 32; kc++) {
        if (kc == 31) { CP_WAIT(0); } else { CP_WAIT(1); }
        __syncthreads();
        if (kc + 2 < 32) { GCOPY(stn, kc + 2); CP_COMMIT(); }
        const uint32_t sb = smb + st * G_STAGE;

        #pragma unroll
        for (int ks = 0; ks < 2; ks++) {
            uint32_t aH[4][4], aL[4][4], bH[8], bL[8];
            #pragma unroll
            for (int mi = 0; mi < 4; mi++) {
                uint32_t ad = sb + swz64(wm * 64 + mi * 16 + (lane & 15),
                                         ks * 2 + (lane >> 4));
                ldsm4(aH[mi], ad);
                ldsm4(aL[mi], ad + 8192);
            }
            #pragma unroll
            for (int p = 0; p < 2; p++) {
                uint32_t bd = sb + 16384 +
                    swz64(wn * 32 + p * 16 + (lane & 7) + ((lane >> 4) & 1) * 8,
                          ks * 2 + ((lane >> 3) & 1));
                ldsm4(&bH[p * 4], bd);
                ldsm4(&bL[p * 4], bd + 8192);
            }
            // term-outer: 16 independent mma between accumulator reuses
            #pragma unroll
            for (int mi = 0; mi < 4; mi++)
                #pragma unroll
                for (int ni = 0; ni < 4; ni++)
                    mmabf(acc[mi][ni], aH[mi], &bH[ni * 2]);
            #pragma unroll
            for (int mi = 0; mi < 4; mi++)
                #pragma unroll
                for (int ni = 0; ni < 4; ni++)
                    mmabf(acc[mi][ni], aH[mi], &bL[ni * 2]);
            #pragma unroll
            for (int mi = 0; mi < 4; mi++)
                #pragma unroll
                for (int ni = 0; ni < 4; ni++)
                    mmabf(acc[mi][ni], aL[mi], &bH[ni * 2]);
        }
        __syncthreads();
        st = (st == 2) ? 0 : st + 1;
        stn = (stn == 2) ? 0 : stn + 1;
    }
    #undef GCOPY

    // epilogue
    const float scale = (mode == 0 && z == 0) ? QSCALE : 1.0f;
    __nv_bfloat16* dh = (z == 0) ? g_Qh : (z == 1) ? g_Kh : g_Vh;
    __nv_bfloat16* dl = (z == 0) ? g_Ql : (z == 1) ? g_Kl : g_Vl;
    #pragma unroll
    for (int mi = 0; mi < 4; mi++)
        #pragma unroll
        for (int ni = 0; ni < 4; ni++) {
            int m0 = brow + wm * 64 + mi * 16 + gq;
            int n0 = bcol + wn * 32 + ni * 8 + 2 * t;
            if (mode == 0) {
                int b = m0 >> 11, s = m0 & 2047;
                int hd = n0 >> 6, d = n0 & 63;
                size_t e0 = (((size_t)(b * NHEAD + hd) * SEQ + s) << 6) + d;
                size_t e1 = (((size_t)(b * NHEAD + hd) * SEQ + (s + 8)) << 6) + d;
                uint32_t uh, ul;
                split2(acc[mi][ni][0] * scale, acc[mi][ni][1] * scale, uh, ul);
                *(uint32_t*)&dh[e0] = uh; *(uint32_t*)&dl[e0] = ul;
                split2(acc[mi][ni][2] * scale, acc[mi][ni][3] * scale, uh, ul);
                *(uint32_t*)&dh[e1] = uh; *(uint32_t*)&dl[e1] = ul;
            } else {
                *(float2*)&Cout[(size_t)m0 * HIDDEN + n0] =
                    make_float2(acc[mi][ni][0], acc[mi][ni][1]);
                *(float2*)&Cout[(size_t)(m0 + 8) * HIDDEN + n0] =
                    make_float2(acc[mi][ni][2], acc[mi][ni][3]);
            }
        }
}

// ---------------------------------------------------------------------------
// Flash attention: 256 q-rows/block, 8 warps x 32 rows, 64-key tiles.
// Q fragments register-cached; P packed in registers; no-max exp2 softmax.
// mma split terms reordered outer (reuse distance 4).
// smem: Qh 0 (32K), Ql 32K, KV stage s at 64K + s*32K:
//       Kh 0 | Kl 8K | Vh 16K | Vl 24K.   Total 128K.
// ---------------------------------------------------------------------------
#define A_SMEM 131072
#define A_KVB(s) (65536 + (s) * 32768)

__global__ __launch_bounds__(256, 1) void attn_bf16()
{
    extern __shared__ char dynsm[];
    const uint32_t smb = smaddr(dynsm);

    const int tid  = threadIdx.x;
    const int lane = tid & 31;
    const int warp = tid >> 5;           // 0..7, rows warp*32..+31
    const int gq   = lane >> 2;
    const int t    = lane & 3;
    const int qt   = blockIdx.x;         // 0..7 (256 rows each)
    const int bh   = blockIdx.y;         // 0..31

    const size_t hb = (size_t)bh << 17;

    // ---- Q tile copy: 256 rows x 128B per component ----
    {
        const char* gqh = (const char*)(g_Qh + hb + ((size_t)qt << 14)) + (size_t)tid * 128;
        const char* gql = (const char*)(g_Ql + hb + ((size_t)qt << 14)) + (size_t)tid * 128;
        #pragma unroll
        for (int i = 0; i < 8; i++) {
            uint32_t sw = swz128(tid, i);
            cpasync16(smb + sw,         gqh + i * 16);
            cpasync16(smb + 32768 + sw, gql + i * 16);
        }
    }
    CP_COMMIT();

    // per-thread K/V copy: row kvr (0..63), chunks kvc, kvc+1 per component
    const int kvr = tid >> 2;
    const int kvc = (tid & 3) << 1;
    const char* gkh = (const char*)(g_Kh + hb) + kvr * 128;
    const char* gkl = (const char*)(g_Kl + hb) + kvr * 128;
    const char* gvh = (const char*)(g_Vh + hb) + kvr * 128;
    const char* gvl = (const char*)(g_Vl + hb) + kvr * 128;
    const uint32_t ksw0 = swz128(kvr, kvc), ksw1 = swz128(kvr, kvc + 1);

    #define KVCOPY(S, KT) do {                                           \
        uint32_t sb_ = smb + A_KVB(S);                                   \
        size_t go_ = (size_t)(KT) * 8192;                                \
        cpasync16(sb_ +     0 + ksw0, gkh + go_ + kvc * 16);             \
        cpasync16(sb_ +  8192 + ksw0, gkl + go_ + kvc * 16);             \
        cpasync16(sb_ + 16384 + ksw0, gvh + go_ + kvc * 16);             \
        cpasync16(sb_ + 24576 + ksw0, gvl + go_ + kvc * 16);             \
        cpasync16(sb_ +     0 + ksw1, gkh + go_ + kvc * 16 + 16);        \
        cpasync16(sb_ +  8192 + ksw1, gkl + go_ + kvc * 16 + 16);        \
        cpasync16(sb_ + 16384 + ksw1, gvh + go_ + kvc * 16 + 16);        \
        cpasync16(sb_ + 24576 + ksw1, gvl + go_ + kvc * 16 + 16);        \
    } while (0)

    KVCOPY(0, 0); CP_COMMIT();
    CP_WAIT(0);
    __syncthreads();

    // ---- cache Q fragments (this warp's 32 rows x 64 cols, hi+lo) ----
    uint32_t qH[2][4][4], qL[2][4][4];
    #pragma unroll
    for (int mb = 0; mb < 2; mb++)
        #pragma unroll
        for (int c = 0; c < 4; c++) {
            uint32_t ad = smb + swz128(warp * 32 + mb * 16 + (lane & 15),
                                       c * 2 + (lane >> 4));
            ldsm4(qH[mb][c], ad);
            ldsm4(qL[mb][c], ad + 32768);
        }

    float accO[2][8][4];
    float lsum[2][2];
    #pragma unroll
    for (int mb = 0; mb < 2; mb++) {
        lsum[mb][0] = 0.f; lsum[mb][1] = 0.f;
        #pragma unroll
        for (int i = 0; i < 8; i++)
            #pragma unroll
            for (int j = 0; j < 4; j++) accO[mb][i][j] = 0.f;
    }

    for (int kt = 0; kt < 32; kt++) {
        CP_WAIT(0);
        __syncthreads();
        if (kt + 1 < 32) { KVCOPY((kt + 1) & 1, kt + 1); CP_COMMIT(); }
        const uint32_t kvb = smb + A_KVB(kt & 1);

        // ---- S = Q K^T  (term-outer mma: 4 independent per acc reuse) ----
        float accS[2][8][4];
        #pragma unroll
        for (int mb = 0; mb < 2; mb++)
            #pragma unroll
            for (int i = 0; i < 8; i++)
                #pragma unroll
                for (int j = 0; j < 4; j++) accS[mb][i][j] = 0.f;

        #pragma unroll
        for (int c = 0; c < 4; c++)
            #pragma unroll
            for (int p = 0; p < 4; p++) {
                uint32_t kh4[4], kl4[4];
                uint32_t bd = kvb +
                    swz128(p * 16 + (lane & 7) + ((lane >> 4) & 1) * 8,
                           c * 2 + ((lane >> 3) & 1));
                ldsm4(kh4, bd);
                ldsm4(kl4, bd + 8192);
                #pragma unroll
                for (int mb = 0; mb < 2; mb++)
                    #pragma unroll
                    for (int h = 0; h < 2; h++)
                        mmabf(accS[mb][2 * p + h], qH[mb][c], &kh4[h * 2]);
                #pragma unroll
                for (int mb = 0; mb < 2; mb++)
                    #pragma unroll
                    for (int h = 0; h < 2; h++)
                        mmabf(accS[mb][2 * p + h], qH[mb][c], &kl4[h * 2]);
                #pragma unroll
                for (int mb = 0; mb < 2; mb++)
                    #pragma unroll
                    for (int h = 0; h < 2; h++)
                        mmabf(accS[mb][2 * p + h], qL[mb][c], &kh4[h * 2]);
            }

        // ---- no-max softmax: P = exp2(S); accumulate row sums ----
        #pragma unroll
        for (int mb = 0; mb < 2; mb++) {
            float r0 = 0.f, r1 = 0.f;
            #pragma unroll
            for (int nt = 0; nt < 8; nt++) {
                accS[mb][nt][0] = ex2(accS[mb][nt][0]);
                accS[mb][nt][1] = ex2(accS[mb][nt][1]);
                accS[mb][nt][2] = ex2(accS[mb][nt][2]);
                accS[mb][nt][3] = ex2(accS[mb][nt][3]);
                r0 += accS[mb][nt][0] + accS[mb][nt][1];
                r1 += accS[mb][nt][2] + accS[mb][nt][3];
            }
            r0 += __shfl_xor_sync(0xffffffffu, r0, 1);
            r0 += __shfl_xor_sync(0xffffffffu, r0, 2);
            r1 += __shfl_xor_sync(0xffffffffu, r1, 1);
            r1 += __shfl_xor_sync(0xffffffffu, r1, 2);
            lsum[mb][0] += r0;
            lsum[mb][1] += r1;
        }

        // ---- O += P V  (term-outer mma) ----
        #pragma unroll
        for (int j = 0; j < 4; j++) {
            uint32_t pH[2][4], pL[2][4];
            #pragma unroll
            for (int mb = 0; mb < 2; mb++) {
                split2(accS[mb][2*j][0],   accS[mb][2*j][1],   pH[mb][0], pL[mb][0]);
                split2(accS[mb][2*j][2],   accS[mb][2*j][3],   pH[mb][1], pL[mb][1]);
                split2(accS[mb][2*j+1][0], accS[mb][2*j+1][1], pH[mb][2], pL[mb][2]);
                split2(accS[mb][2*j+1][2], accS[mb][2*j+1][3], pH[mb][3], pL[mb][3]);
            }
            #pragma unroll
            for (int p = 0; p < 4; p++) {
                uint32_t vh4[4], vl4[4];
                uint32_t vd = kvb + 16384 +
                    swz128(j * 16 + (lane & 15), p * 2 + (lane >> 4));
                ldsm4t(vh4, vd);
                ldsm4t(vl4, vd + 8192);
                #pragma unroll
                for (int mb = 0; mb < 2; mb++)
                    #pragma unroll
                    for (int h = 0; h < 2; h++)
                        mmabf(accO[mb][2 * p + h], pH[mb], &vh4[h * 2]);
                #pragma unroll
                for (int mb = 0; mb < 2; mb++)
                    #pragma unroll
                    for (int h = 0; h < 2; h++)
                        mmabf(accO[mb][2 * p + h], pH[mb], &vl4[h * 2]);
                #pragma unroll
                for (int mb = 0; mb < 2; mb++)
                    #pragma unroll
                    for (int h = 0; h < 2; h++)
                        mmabf(accO[mb][2 * p + h], pL[mb], &vh4[h * 2]);
            }
        }
        __syncthreads();
    }
    #undef KVCOPY

    // ---- epilogue: normalize, split, write g_Oh/g_Ol [b,s,1024] ----
    const int b = bh >> 4, hh = bh & 15;
    #pragma unroll
    for (int mb = 0; mb < 2; mb++) {
        const float i0 = 1.f / lsum[mb][0], i1 = 1.f / lsum[mb][1];
        const int sg = qt * 256 + warp * 32 + mb * 16 + gq;
        #pragma unroll
        for (int nt = 0; nt < 8; nt++) {
            size_t e0 = (size_t)(b * SEQ + sg) * HIDDEN + hh * 64 + nt * 8 + 2 * t;
            size_t e1 = e0 + (size_t)8 * HIDDEN;
            uint32_t h, l;
            split2(accO[mb][nt][0] * i0, accO[mb][nt][1] * i0, h, l);
            *(uint32_t*)&g_Oh[e0] = h; *(uint32_t*)&g_Ol[e0] = l;
            split2(accO[mb][nt][2] * i1, accO[mb][nt][3] * i1, h, l);
            *(uint32_t*)&g_Oh[e1] = h; *(uint32_t*)&g_Ol[e1] = l;
        }
    }
}

// ---------------------------------------------------------------------------
extern "C" void kernel_launch(void* const* d_in, const int* in_sizes, int n_in,
                              void* d_out, int out_size)
{
    const float* x  = (const float*)d_in[0];
    const float* Wq = (const float*)d_in[1];
    const float* Wk = (const float*)d_in[2];
    const float* Wv = (const float*)d_in[3];
    const float* Wo = (const float*)d_in[4];
    float* out = (float*)d_out;

    static int inited = 0;
    if (!inited) {
        cudaFuncSetAttribute(gemm_bf16,
            cudaFuncAttributeMaxDynamicSharedMemorySize, G_SMEM);
        cudaFuncSetAttribute(attn_bf16,
            cudaFuncAttributeMaxDynamicSharedMemorySize, A_SMEM);
        inited = 1;
    }

    // 0) convert inputs to bf16 hi/lo pool
    convert_kernel<<<CVT_TOTAL / 4 / 256, 256>>>(x, Wq, Wk, Wv, Wo);

    {
        __nv_bfloat16 *cH, *cL;
        cudaGetSymbolAddress((void**)&cH, g_cvtH);
        cudaGetSymbolAddress((void**)&cL, g_cvtL);

        // 1) Q,K,V projections
        dim3 gqkv(HIDDEN / 128, MROWS / 128, 3);
        gemm_bf16<<<gqkv, 256, G_SMEM>>>(cH + XOFF, cL + XOFF,
                                         cH + WOFF, cL + WOFF, nullptr, 0);

        // 2) fused flash attention -> g_Oh/g_Ol
        dim3 gattn(SEQ / 256, BATCH * NHEAD, 1);
        attn_bf16<<<gattn, 256, A_SMEM>>>();

        // 3) output projection -> d_out
        __nv_bfloat16 *oH, *oL;
        cudaGetSymbolAddress((void**)&oH, g_Oh);
        cudaGetSymbolAddress((void**)&oL, g_Ol);
        dim3 gout(HIDDEN / 128, MROWS / 128, 1);
        gemm_bf16<<<gout, 256, G_SMEM>>>(oH, oL,
                                         cH + WOFF + 3 * WSZ, cL + WOFF + 3 * WSZ,
                                         out, 1);
    }
}